// round 2
// baseline (speedup 1.0000x reference)
#include <cuda_runtime.h>
#include <math.h>

// ---------------------------------------------------------------------------
// Attention_28372553957894 — fp32 SIMT baseline
//   q = relu(x@Wq+bq); k = relu(x@Wk+bk); v = q
//   S[b,n,m] = k[b,n,:] . q[b,m,:]
//   P = softmax over m (row-softmax of S)
//   att[b,m,h] = sum_n P[b,n,m] * v[b,n,h]
//   out = relu(att@Wm+bm)
// Shapes: B=8, N=2048, CIN=H=UNITS=256
// ---------------------------------------------------------------------------

#define Bsz   8
#define SEQ   2048
#define CH    256          // CIN == H == UNITS
#define MTOT  (Bsz*SEQ)    // 16384

#define BM 128
#define BN 128
#define BK 16
#define TM 8
#define TN 8
// 256 threads per block, 16x16 thread grid, each thread 8x8 outputs

// scratch (device globals: allocation-free per harness rules)
__device__ float g_Q[MTOT * CH];                     // 16.8 MB
__device__ float g_K[MTOT * CH];                     // 16.8 MB
__device__ float g_S[Bsz * SEQ * SEQ];               // 134 MB
__device__ float g_ATT[MTOT * CH];                   // 16.8 MB

// ---------------------------------------------------------------------------
// NN GEMM: C[M,N] = relu(A[M,K] @ B[K,N] + bias[N])   (row-major everywhere)
// K and N are multiples of BK/BN; M multiple of BM.
// ---------------------------------------------------------------------------
__global__ __launch_bounds__(256)
void gemm_nn_bias_relu(const float* __restrict__ A, const float* __restrict__ B,
                       const float* __restrict__ bias, float* __restrict__ C,
                       int M, int N, int K) {
    __shared__ float As[BK][BM];
    __shared__ float Bs[BK][BN];

    const int tid = threadIdx.x;
    const int tx  = tid & 15;          // 0..15 -> output cols
    const int ty  = tid >> 4;          // 0..15 -> output rows
    const int m0  = blockIdx.y * BM;
    const int n0  = blockIdx.x * BN;

    float acc[TM][TN] = {};

    for (int k0 = 0; k0 < K; k0 += BK) {
        // load A tile (BM x BK) transposed into As[k][m]; 512 float4, 2/thread
        #pragma unroll
        for (int i = 0; i < 2; i++) {
            int idx = tid + i * 256;          // 0..511
            int r   = idx >> 2;               // row 0..127
            int c4  = idx & 3;                // float4 index in 16 cols
            float4 v = *(const float4*)(A + (size_t)(m0 + r) * K + k0 + c4 * 4);
            As[c4 * 4 + 0][r] = v.x;
            As[c4 * 4 + 1][r] = v.y;
            As[c4 * 4 + 2][r] = v.z;
            As[c4 * 4 + 3][r] = v.w;
        }
        // load B tile (BK x BN) directly; 512 float4, 2/thread
        #pragma unroll
        for (int i = 0; i < 2; i++) {
            int idx = tid + i * 256;
            int r   = idx >> 5;               // k row 0..15
            int c4  = idx & 31;               // float4 col
            *(float4*)&Bs[r][c4 * 4] =
                *(const float4*)(B + (size_t)(k0 + r) * N + n0 + c4 * 4);
        }
        __syncthreads();

        #pragma unroll
        for (int k = 0; k < BK; k++) {
            float a[TM], b[TN];
            #pragma unroll
            for (int i = 0; i < TM; i++) a[i] = As[k][ty * TM + i];
            #pragma unroll
            for (int j = 0; j < TN; j++) b[j] = Bs[k][tx * TN + j];
            #pragma unroll
            for (int i = 0; i < TM; i++)
                #pragma unroll
                for (int j = 0; j < TN; j++)
                    acc[i][j] += a[i] * b[j];
        }
        __syncthreads();
    }

    const int row0 = m0 + ty * TM;
    const int col0 = n0 + tx * TN;
    float bv[TN];
    #pragma unroll
    for (int j = 0; j < TN; j++) bv[j] = bias[col0 + j];
    #pragma unroll
    for (int i = 0; i < TM; i++) {
        #pragma unroll
        for (int j = 0; j < TN; j += 4) {
            float4 v;
            v.x = fmaxf(acc[i][j + 0] + bv[j + 0], 0.0f);
            v.y = fmaxf(acc[i][j + 1] + bv[j + 1], 0.0f);
            v.z = fmaxf(acc[i][j + 2] + bv[j + 2], 0.0f);
            v.w = fmaxf(acc[i][j + 3] + bv[j + 3], 0.0f);
            *(float4*)(C + (size_t)(row0 + i) * N + col0 + j) = v;
        }
    }
}

// ---------------------------------------------------------------------------
// NT GEMM (per batch z): S[n,m] = sum_h K[n,h] * Q[m,h]
// K,Q: (SEQ, CH) row-major. S: (SEQ, SEQ).
// ---------------------------------------------------------------------------
__global__ __launch_bounds__(256)
void gemm_nt_s(const float* __restrict__ Kg, const float* __restrict__ Qg,
               float* __restrict__ Sg) {
    const int b = blockIdx.z;
    const float* A = Kg + (size_t)b * SEQ * CH;   // rows n
    const float* B = Qg + (size_t)b * SEQ * CH;   // rows m
    float*       C = Sg + (size_t)b * SEQ * SEQ;

    __shared__ float As[BK][BM];
    __shared__ float Bs[BK][BN];

    const int tid = threadIdx.x;
    const int tx  = tid & 15;
    const int ty  = tid >> 4;
    const int n0  = blockIdx.y * BM;
    const int m0  = blockIdx.x * BN;

    float acc[TM][TN] = {};

    for (int k0 = 0; k0 < CH; k0 += BK) {
        #pragma unroll
        for (int i = 0; i < 2; i++) {
            int idx = tid + i * 256;
            int r   = idx >> 2;
            int c4  = idx & 3;
            float4 va = *(const float4*)(A + (size_t)(n0 + r) * CH + k0 + c4 * 4);
            As[c4 * 4 + 0][r] = va.x;
            As[c4 * 4 + 1][r] = va.y;
            As[c4 * 4 + 2][r] = va.z;
            As[c4 * 4 + 3][r] = va.w;
            float4 vb = *(const float4*)(B + (size_t)(m0 + r) * CH + k0 + c4 * 4);
            Bs[c4 * 4 + 0][r] = vb.x;
            Bs[c4 * 4 + 1][r] = vb.y;
            Bs[c4 * 4 + 2][r] = vb.z;
            Bs[c4 * 4 + 3][r] = vb.w;
        }
        __syncthreads();

        #pragma unroll
        for (int k = 0; k < BK; k++) {
            float a[TM], bb[TN];
            #pragma unroll
            for (int i = 0; i < TM; i++) a[i] = As[k][ty * TM + i];
            #pragma unroll
            for (int j = 0; j < TN; j++) bb[j] = Bs[k][tx * TN + j];
            #pragma unroll
            for (int i = 0; i < TM; i++)
                #pragma unroll
                for (int j = 0; j < TN; j++)
                    acc[i][j] += a[i] * bb[j];
        }
        __syncthreads();
    }

    const int row0 = n0 + ty * TM;
    const int col0 = m0 + tx * TN;
    #pragma unroll
    for (int i = 0; i < TM; i++) {
        #pragma unroll
        for (int j = 0; j < TN; j += 4) {
            float4 v;
            v.x = acc[i][j + 0];
            v.y = acc[i][j + 1];
            v.z = acc[i][j + 2];
            v.w = acc[i][j + 3];
            *(float4*)(C + (size_t)(row0 + i) * SEQ + col0 + j) = v;
        }
    }
}

// ---------------------------------------------------------------------------
// Row softmax over the last axis (m). One block per (b,n) row of 2048.
// ---------------------------------------------------------------------------
__global__ __launch_bounds__(256)
void softmax_rows(float* __restrict__ S) {
    const size_t row = blockIdx.x;
    float* p = S + row * (size_t)SEQ;
    const int tid = threadIdx.x;

    float v[8];
    float mx = -INFINITY;
    #pragma unroll
    for (int i = 0; i < 8; i++) {
        v[i] = p[tid + i * 256];
        mx = fmaxf(mx, v[i]);
    }

    __shared__ float red_max[8];
    __shared__ float red_sum[8];

    #pragma unroll
    for (int o = 16; o > 0; o >>= 1) mx = fmaxf(mx, __shfl_xor_sync(0xffffffffu, mx, o));
    if ((tid & 31) == 0) red_max[tid >> 5] = mx;
    __syncthreads();
    if (tid < 32) {
        float t = (tid < 8) ? red_max[tid] : -INFINITY;
        #pragma unroll
        for (int o = 4; o > 0; o >>= 1) t = fmaxf(t, __shfl_xor_sync(0xffffffffu, t, o));
        if (tid == 0) red_max[0] = t;
    }
    __syncthreads();
    mx = red_max[0];

    float s = 0.0f;
    #pragma unroll
    for (int i = 0; i < 8; i++) {
        v[i] = __expf(v[i] - mx);
        s += v[i];
    }
    #pragma unroll
    for (int o = 16; o > 0; o >>= 1) s += __shfl_xor_sync(0xffffffffu, s, o);
    if ((tid & 31) == 0) red_sum[tid >> 5] = s;
    __syncthreads();
    if (tid < 32) {
        float t = (tid < 8) ? red_sum[tid] : 0.0f;
        #pragma unroll
        for (int o = 4; o > 0; o >>= 1) t += __shfl_xor_sync(0xffffffffu, t, o);
        if (tid == 0) red_sum[0] = t;
    }
    __syncthreads();
    const float inv = 1.0f / red_sum[0];

    #pragma unroll
    for (int i = 0; i < 8; i++) p[tid + i * 256] = v[i] * inv;
}

// ---------------------------------------------------------------------------
// TN GEMM (per batch z): ATT[m,h] = sum_n P[n,m] * V[n,h]
// P: (SEQ, SEQ) row-major; V: (SEQ, CH) row-major; ATT: (SEQ, CH).
// ---------------------------------------------------------------------------
__global__ __launch_bounds__(256)
void gemm_tn_att(const float* __restrict__ Sg, const float* __restrict__ Vg,
                 float* __restrict__ ATTg) {
    const int b = blockIdx.z;
    const float* P = Sg + (size_t)b * SEQ * SEQ;
    const float* V = Vg + (size_t)b * SEQ * CH;
    float*       C = ATTg + (size_t)b * SEQ * CH;

    __shared__ float Ps[BK][BM];
    __shared__ float Vs[BK][BN];

    const int tid = threadIdx.x;
    const int tx  = tid & 15;
    const int ty  = tid >> 4;
    const int m0  = blockIdx.y * BM;   // output rows (m)
    const int h0  = blockIdx.x * BN;   // output cols (h)

    float acc[TM][TN] = {};

    for (int n0 = 0; n0 < SEQ; n0 += BK) {
        #pragma unroll
        for (int i = 0; i < 2; i++) {
            int idx = tid + i * 256;
            int r   = idx >> 5;       // n within tile 0..15
            int c4  = idx & 31;       // float4 col
            *(float4*)&Ps[r][c4 * 4] =
                *(const float4*)(P + (size_t)(n0 + r) * SEQ + m0 + c4 * 4);
            *(float4*)&Vs[r][c4 * 4] =
                *(const float4*)(V + (size_t)(n0 + r) * CH + h0 + c4 * 4);
        }
        __syncthreads();

        #pragma unroll
        for (int k = 0; k < BK; k++) {
            float a[TM], bb[TN];
            #pragma unroll
            for (int i = 0; i < TM; i++) a[i] = Ps[k][ty * TM + i];
            #pragma unroll
            for (int j = 0; j < TN; j++) bb[j] = Vs[k][tx * TN + j];
            #pragma unroll
            for (int i = 0; i < TM; i++)
                #pragma unroll
                for (int j = 0; j < TN; j++)
                    acc[i][j] += a[i] * bb[j];
        }
        __syncthreads();
    }

    const int row0 = m0 + ty * TM;
    const int col0 = h0 + tx * TN;
    #pragma unroll
    for (int i = 0; i < TM; i++) {
        #pragma unroll
        for (int j = 0; j < TN; j += 4) {
            float4 v;
            v.x = acc[i][j + 0];
            v.y = acc[i][j + 1];
            v.z = acc[i][j + 2];
            v.w = acc[i][j + 3];
            *(float4*)(C + (size_t)(row0 + i) * CH + col0 + j) = v;
        }
    }
}

// ---------------------------------------------------------------------------
// launch
// ---------------------------------------------------------------------------
extern "C" void kernel_launch(void* const* d_in, const int* in_sizes, int n_in,
                              void* d_out, int out_size) {
    const float* x  = (const float*)d_in[0];
    const float* Wq = (const float*)d_in[1];
    const float* bq = (const float*)d_in[2];
    const float* Wk = (const float*)d_in[3];
    const float* bk = (const float*)d_in[4];
    const float* Wm = (const float*)d_in[5];
    const float* bm = (const float*)d_in[6];
    float* out = (float*)d_out;

    float *Q, *K, *S, *ATT;
    cudaGetSymbolAddress((void**)&Q,   g_Q);
    cudaGetSymbolAddress((void**)&K,   g_K);
    cudaGetSymbolAddress((void**)&S,   g_S);
    cudaGetSymbolAddress((void**)&ATT, g_ATT);

    const dim3 blk(256);

    // Stage 1: projections q, k
    const dim3 g1(CH / BN, MTOT / BM);                 // (2, 128)
    gemm_nn_bias_relu<<<g1, blk>>>(x, Wq, bq, Q, MTOT, CH, CH);
    gemm_nn_bias_relu<<<g1, blk>>>(x, Wk, bk, K, MTOT, CH, CH);

    // Stage 2: S = K @ Q^T per batch
    const dim3 g2(SEQ / BN, SEQ / BM, Bsz);            // (16, 16, 8)
    gemm_nt_s<<<g2, blk>>>(K, Q, S);

    // Stage 3: row softmax over m
    softmax_rows<<<Bsz * SEQ, blk>>>(S);

    // Stage 4: ATT = P^T @ V  (V = Q)
    const dim3 g3(CH / BN, SEQ / BM, Bsz);             // (2, 16, 8)
    gemm_tn_att<<<g3, blk>>>(S, Q, ATT);

    // Stage 5: out = relu(ATT @ Wm + bm)
    gemm_nn_bias_relu<<<g1, blk>>>(ATT, Wm, bm, out, MTOT, CH, CH);
}

// round 4
// speedup vs baseline: 1.8371x; 1.8371x over previous
#include <cuda_runtime.h>
#include <cuda_bf16.h>
#include <math.h>
#include <stdint.h>

// ---------------------------------------------------------------------------
// Attention_28372553957894 — R4: mma.sync (HMMA) bf16-split big GEMMs
//   q = relu(x@Wq+bq); k = relu(x@Wk+bk); v = q            (SIMT fp32)
//   S[b,n,m] = k_n . q_m                                    (mma.sync, 3xbf16)
//   P = softmax_m(S)                                        (SIMT)
//   att[b,m,h] = sum_n P[n,m] v[n,h]                        (mma.sync, 3xbf16)
//   out = relu(att@Wm+bm)                                   (SIMT fp32)
// ---------------------------------------------------------------------------

#define Bsz   8
#define SEQ   2048
#define CH    256
#define MTOT  (Bsz*SEQ)

#define BM 128
#define BN 128
#define BK 16
#define TM 8
#define TN 8

__device__ float g_Q[MTOT * CH];
__device__ float g_K[MTOT * CH];
__device__ float g_S[Bsz * SEQ * SEQ];
__device__ float g_ATT[MTOT * CH];

// ===========================================================================
// helpers
// ===========================================================================
__device__ __forceinline__ uint32_t s2u(const void* p) {
    uint32_t a;
    asm("{ .reg .u64 t; cvta.to.shared.u64 t, %1; cvt.u32.u64 %0, t; }"
        : "=r"(a) : "l"(p));
    return a;
}
// 128B-row tiles: XOR row&7 into 16B-chunk bits
__device__ __forceinline__ uint32_t swz(uint32_t o)    { return o ^ ((o >> 3) & 0x70); }
// 256B-row tiles: row bits are 8..13 -> XOR row&7 (bits 8-10) into bits 4-6
__device__ __forceinline__ uint32_t swz256(uint32_t o) { return o ^ ((o >> 4) & 0x70); }

__device__ __forceinline__ void ldsm_x4(uint32_t& r0, uint32_t& r1, uint32_t& r2,
                                        uint32_t& r3, uint32_t addr) {
    asm volatile("ldmatrix.sync.aligned.m8n8.x4.shared.b16 {%0,%1,%2,%3}, [%4];"
                 : "=r"(r0), "=r"(r1), "=r"(r2), "=r"(r3) : "r"(addr));
}
__device__ __forceinline__ void ldsm_x4t(uint32_t& r0, uint32_t& r1, uint32_t& r2,
                                         uint32_t& r3, uint32_t addr) {
    asm volatile("ldmatrix.sync.aligned.m8n8.x4.trans.shared.b16 {%0,%1,%2,%3}, [%4];"
                 : "=r"(r0), "=r"(r1), "=r"(r2), "=r"(r3) : "r"(addr));
}

#define MMA16816(c, a, b0v, b1v)                                               \
    asm volatile(                                                              \
        "mma.sync.aligned.m16n8k16.row.col.f32.bf16.bf16.f32 "                 \
        "{%0,%1,%2,%3}, {%4,%5,%6,%7}, {%8,%9}, {%0,%1,%2,%3};"                \
        : "+f"((c)[0]), "+f"((c)[1]), "+f"((c)[2]), "+f"((c)[3])               \
        : "r"((a)[0]), "r"((a)[1]), "r"((a)[2]), "r"((a)[3]),                  \
          "r"(b0v), "r"(b1v))

__device__ __forceinline__ uint32_t pack_bf2(__nv_bfloat16 a, __nv_bfloat16 b) {
    __nv_bfloat162 t = __halves2bfloat162(a, b);
    return *reinterpret_cast<uint32_t*>(&t);
}
__device__ __forceinline__ void split1(float x, __nv_bfloat16& h, __nv_bfloat16& l) {
    h = __float2bfloat16(x);
    l = __float2bfloat16(x - __bfloat162float(h));
}

// SMEM tile offsets (16 KB each)
#define SM_A_HI  0
#define SM_A_LO  16384
#define SM_B_HI  32768
#define SM_B_LO  49152
#define SMEM_TC_BYTES 65536

// ===========================================================================
// S = K @ Q^T per batch.  CTA tile: 128 n-rows x 128 m-cols. k over CH=256.
// Operands staged k-major (128 rows x 64 k-cols bf16, 128B rows, swz).
// ===========================================================================
__global__ __launch_bounds__(256)
void gemm_s_tc(const float* __restrict__ Kg, const float* __restrict__ Qg,
               float* __restrict__ Sg) {
    extern __shared__ char smem[];
    const uint32_t sb = s2u(smem);
    const int tid = threadIdx.x, lane = tid & 31, wid = tid >> 5;
    const int b  = blockIdx.z;
    const int m0 = blockIdx.x * 128;
    const int n0 = blockIdx.y * 128;
    const float* A = Kg + (size_t)b * SEQ * CH;   // rows n
    const float* B = Qg + (size_t)b * SEQ * CH;   // rows m
    float*       C = Sg + (size_t)b * SEQ * SEQ;

    const int wm = (wid & 3) * 32;   // warp n-offset (MMA M)
    const int wn = (wid >> 2) * 64;  // warp m-offset (MMA N)

    float acc[2][8][4] = {};

    for (int kc = 0; kc < 4; kc++) {
        const int k0 = kc * 64;
        // ---- stage A (K rows) and B (Q rows): 128x64 fp32 -> hi/lo bf16
        #pragma unroll
        for (int i = 0; i < 8; i++) {
            int e = tid + i * 256, r = e >> 4, c4 = e & 15;
            uint32_t so = swz((uint32_t)(r * 128 + c4 * 8));
            {
                float4 v = *(const float4*)(A + (size_t)(n0 + r) * CH + k0 + c4 * 4);
                __nv_bfloat16 h0,h1,h2,h3,l0,l1,l2,l3;
                split1(v.x,h0,l0); split1(v.y,h1,l1); split1(v.z,h2,l2); split1(v.w,h3,l3);
                uint2 uh = { pack_bf2(h0,h1), pack_bf2(h2,h3) };
                uint2 ul = { pack_bf2(l0,l1), pack_bf2(l2,l3) };
                *(uint2*)(smem + SM_A_HI + so) = uh;
                *(uint2*)(smem + SM_A_LO + so) = ul;
            }
            {
                float4 v = *(const float4*)(B + (size_t)(m0 + r) * CH + k0 + c4 * 4);
                __nv_bfloat16 h0,h1,h2,h3,l0,l1,l2,l3;
                split1(v.x,h0,l0); split1(v.y,h1,l1); split1(v.z,h2,l2); split1(v.w,h3,l3);
                uint2 uh = { pack_bf2(h0,h1), pack_bf2(h2,h3) };
                uint2 ul = { pack_bf2(l0,l1), pack_bf2(l2,l3) };
                *(uint2*)(smem + SM_B_HI + so) = uh;
                *(uint2*)(smem + SM_B_LO + so) = ul;
            }
        }
        __syncthreads();

        // ---- compute 4 k16 steps
        #pragma unroll
        for (int ks = 0; ks < 4; ks++) {
            const uint32_t kb  = ks * 32;                 // byte offset of k16
            const uint32_t sel = (lane >> 4) << 4;        // 0 / 16B half
            uint32_t ao0 = swz((uint32_t)((wm +      (lane & 15)) * 128) + kb + sel);
            uint32_t ao1 = swz((uint32_t)((wm + 16 + (lane & 15)) * 128) + kb + sel);
            uint32_t ah0[4], al0[4], ah1[4], al1[4];
            ldsm_x4(ah0[0],ah0[1],ah0[2],ah0[3], sb + SM_A_HI + ao0);
            ldsm_x4(al0[0],al0[1],al0[2],al0[3], sb + SM_A_LO + ao0);
            ldsm_x4(ah1[0],ah1[1],ah1[2],ah1[3], sb + SM_A_HI + ao1);
            ldsm_x4(al1[0],al1[1],al1[2],al1[3], sb + SM_A_LO + ao1);
            #pragma unroll
            for (int nq = 0; nq < 4; nq++) {
                uint32_t bo = swz((uint32_t)((wn + nq * 16 + (lane & 15)) * 128) + kb + sel);
                uint32_t bh[4], bl[4];
                ldsm_x4(bh[0],bh[1],bh[2],bh[3], sb + SM_B_HI + bo);
                ldsm_x4(bl[0],bl[1],bl[2],bl[3], sb + SM_B_LO + bo);
                // group g0={r0,r2}, g1={r1,r3}
                MMA16816(acc[0][nq*2  ], ah0, bh[0], bh[2]);
                MMA16816(acc[0][nq*2  ], ah0, bl[0], bl[2]);
                MMA16816(acc[0][nq*2  ], al0, bh[0], bh[2]);
                MMA16816(acc[0][nq*2+1], ah0, bh[1], bh[3]);
                MMA16816(acc[0][nq*2+1], ah0, bl[1], bl[3]);
                MMA16816(acc[0][nq*2+1], al0, bh[1], bh[3]);
                MMA16816(acc[1][nq*2  ], ah1, bh[0], bh[2]);
                MMA16816(acc[1][nq*2  ], ah1, bl[0], bl[2]);
                MMA16816(acc[1][nq*2  ], al1, bh[0], bh[2]);
                MMA16816(acc[1][nq*2+1], ah1, bh[1], bh[3]);
                MMA16816(acc[1][nq*2+1], ah1, bl[1], bl[3]);
                MMA16816(acc[1][nq*2+1], al1, bh[1], bh[3]);
            }
        }
        __syncthreads();
    }

    // ---- epilogue
    #pragma unroll
    for (int mi = 0; mi < 2; mi++) {
        #pragma unroll
        for (int g = 0; g < 8; g++) {
            const int row = n0 + wm + mi * 16 + (lane >> 2);
            const int col = m0 + wn + g * 8 + (lane & 3) * 2;
            float2 v0 = { acc[mi][g][0], acc[mi][g][1] };
            float2 v1 = { acc[mi][g][2], acc[mi][g][3] };
            *(float2*)(C + (size_t)row * SEQ + col)        = v0;
            *(float2*)(C + (size_t)(row + 8) * SEQ + col)  = v1;
        }
    }
}

// ===========================================================================
// ATT[m,h] = sum_n P[n,m] V[n,h] per batch. CTA: 128 m x 128 h. n in 64-chunks.
// P, V staged contraction-major (64 n-rows x 128 cols, 256B rows, swz256);
// ldmatrix.trans supplies the transposed fragments.
// ===========================================================================
__global__ __launch_bounds__(256)
void gemm_att_tc(const float* __restrict__ Pg, const float* __restrict__ Vg,
                 float* __restrict__ ATTg) {
    extern __shared__ char smem[];
    const uint32_t sb = s2u(smem);
    const int tid = threadIdx.x, lane = tid & 31, wid = tid >> 5;
    const int b  = blockIdx.z;
    const int m0 = blockIdx.x * 128;
    const int h0 = blockIdx.y * 128;
    const float* P = Pg + (size_t)b * SEQ * SEQ;
    const float* V = Vg + (size_t)b * SEQ * CH;
    float*       C = ATTg + (size_t)b * SEQ * CH;

    const int wm = (wid & 3) * 32;   // warp m-offset (MMA M)
    const int wn = (wid >> 2) * 64;  // warp h-offset (MMA N)

    float acc[2][8][4] = {};

    for (int kc = 0; kc < 32; kc++) {
        const int nb = kc * 64;
        // ---- stage P chunk [64][128 m] and V chunk [64][128 h], no transpose
        #pragma unroll
        for (int i = 0; i < 8; i++) {
            int e = tid + i * 256, r = e >> 5, c4 = e & 31;
            uint32_t so = swz256((uint32_t)(r * 256 + c4 * 8));
            {
                float4 v = *(const float4*)(P + (size_t)(nb + r) * SEQ + m0 + c4 * 4);
                __nv_bfloat16 h0_,h1_,h2_,h3_,l0_,l1_,l2_,l3_;
                split1(v.x,h0_,l0_); split1(v.y,h1_,l1_); split1(v.z,h2_,l2_); split1(v.w,h3_,l3_);
                uint2 uh = { pack_bf2(h0_,h1_), pack_bf2(h2_,h3_) };
                uint2 ul = { pack_bf2(l0_,l1_), pack_bf2(l2_,l3_) };
                *(uint2*)(smem + SM_A_HI + so) = uh;
                *(uint2*)(smem + SM_A_LO + so) = ul;
            }
            {
                float4 v = *(const float4*)(V + (size_t)(nb + r) * CH + h0 + c4 * 4);
                __nv_bfloat16 h0_,h1_,h2_,h3_,l0_,l1_,l2_,l3_;
                split1(v.x,h0_,l0_); split1(v.y,h1_,l1_); split1(v.z,h2_,l2_); split1(v.w,h3_,l3_);
                uint2 uh = { pack_bf2(h0_,h1_), pack_bf2(h2_,h3_) };
                uint2 ul = { pack_bf2(l0_,l1_), pack_bf2(l2_,l3_) };
                *(uint2*)(smem + SM_B_HI + so) = uh;
                *(uint2*)(smem + SM_B_LO + so) = ul;
            }
        }
        __syncthreads();

        #pragma unroll
        for (int ks = 0; ks < 4; ks++) {
            const int kk = ks * 16;                       // n-row within chunk
            // A (P^T) fragments via trans ldmatrix
            uint32_t ah0[4], al0[4], ah1[4], al1[4];
            {
                const int arow = kk + ((lane >> 4) << 3) + (lane & 7);
                #pragma unroll
                for (int mi = 0; mi < 2; mi++) {
                    const int acol = wm + mi * 16 + (((lane >> 3) & 1) << 3);
                    uint32_t ao = swz256((uint32_t)(arow * 256 + acol * 2));
                    if (mi == 0) {
                        ldsm_x4t(ah0[0],ah0[1],ah0[2],ah0[3], sb + SM_A_HI + ao);
                        ldsm_x4t(al0[0],al0[1],al0[2],al0[3], sb + SM_A_LO + ao);
                    } else {
                        ldsm_x4t(ah1[0],ah1[1],ah1[2],ah1[3], sb + SM_A_HI + ao);
                        ldsm_x4t(al1[0],al1[1],al1[2],al1[3], sb + SM_A_LO + ao);
                    }
                }
            }
            #pragma unroll
            for (int nq = 0; nq < 4; nq++) {
                const int brow = kk + (lane & 15);
                const int bcol = wn + nq * 16 + ((lane >> 4) << 3);
                uint32_t bo = swz256((uint32_t)(brow * 256 + bcol * 2));
                uint32_t bh[4], bl[4];
                ldsm_x4t(bh[0],bh[1],bh[2],bh[3], sb + SM_B_HI + bo);
                ldsm_x4t(bl[0],bl[1],bl[2],bl[3], sb + SM_B_LO + bo);
                // trans x4 groups: g0={r0,r1}, g1={r2,r3}
                MMA16816(acc[0][nq*2  ], ah0, bh[0], bh[1]);
                MMA16816(acc[0][nq*2  ], ah0, bl[0], bl[1]);
                MMA16816(acc[0][nq*2  ], al0, bh[0], bh[1]);
                MMA16816(acc[0][nq*2+1], ah0, bh[2], bh[3]);
                MMA16816(acc[0][nq*2+1], ah0, bl[2], bl[3]);
                MMA16816(acc[0][nq*2+1], al0, bh[2], bh[3]);
                MMA16816(acc[1][nq*2  ], ah1, bh[0], bh[1]);
                MMA16816(acc[1][nq*2  ], ah1, bl[0], bl[1]);
                MMA16816(acc[1][nq*2  ], al1, bh[0], bh[1]);
                MMA16816(acc[1][nq*2+1], ah1, bh[2], bh[3]);
                MMA16816(acc[1][nq*2+1], ah1, bl[2], bl[3]);
                MMA16816(acc[1][nq*2+1], al1, bh[2], bh[3]);
            }
        }
        __syncthreads();
    }

    #pragma unroll
    for (int mi = 0; mi < 2; mi++) {
        #pragma unroll
        for (int g = 0; g < 8; g++) {
            const int row = m0 + wm + mi * 16 + (lane >> 2);
            const int col = h0 + wn + g * 8 + (lane & 3) * 2;
            float2 v0 = { acc[mi][g][0], acc[mi][g][1] };
            float2 v1 = { acc[mi][g][2], acc[mi][g][3] };
            *(float2*)(C + (size_t)row * CH + col)       = v0;
            *(float2*)(C + (size_t)(row + 8) * CH + col) = v1;
        }
    }
}

// ===========================================================================
// SIMT fp32 NN GEMM with bias + relu
// ===========================================================================
__global__ __launch_bounds__(256)
void gemm_nn_bias_relu(const float* __restrict__ A, const float* __restrict__ B,
                       const float* __restrict__ bias, float* __restrict__ C,
                       int M, int N, int K) {
    __shared__ float As[BK][BM];
    __shared__ float Bs[BK][BN];
    const int tid = threadIdx.x;
    const int tx  = tid & 15;
    const int ty  = tid >> 4;
    const int m0  = blockIdx.y * BM;
    const int n0  = blockIdx.x * BN;
    float acc[TM][TN] = {};
    for (int k0 = 0; k0 < K; k0 += BK) {
        #pragma unroll
        for (int i = 0; i < 2; i++) {
            int idx = tid + i * 256;
            int r = idx >> 2, c4 = idx & 3;
            float4 v = *(const float4*)(A + (size_t)(m0 + r) * K + k0 + c4 * 4);
            As[c4*4+0][r] = v.x; As[c4*4+1][r] = v.y;
            As[c4*4+2][r] = v.z; As[c4*4+3][r] = v.w;
        }
        #pragma unroll
        for (int i = 0; i < 2; i++) {
            int idx = tid + i * 256;
            int r = idx >> 5, c4 = idx & 31;
            *(float4*)&Bs[r][c4*4] = *(const float4*)(B + (size_t)(k0 + r) * N + n0 + c4*4);
        }
        __syncthreads();
        #pragma unroll
        for (int k = 0; k < BK; k++) {
            float a[TM], b[TN];
            #pragma unroll
            for (int i = 0; i < TM; i++) a[i] = As[k][ty*TM+i];
            #pragma unroll
            for (int j = 0; j < TN; j++) b[j] = Bs[k][tx*TN+j];
            #pragma unroll
            for (int i = 0; i < TM; i++)
                #pragma unroll
                for (int j = 0; j < TN; j++)
                    acc[i][j] += a[i] * b[j];
        }
        __syncthreads();
    }
    const int row0 = m0 + ty*TM, col0 = n0 + tx*TN;
    float bv[TN];
    #pragma unroll
    for (int j = 0; j < TN; j++) bv[j] = bias[col0 + j];
    #pragma unroll
    for (int i = 0; i < TM; i++) {
        #pragma unroll
        for (int j = 0; j < TN; j += 4) {
            float4 v;
            v.x = fmaxf(acc[i][j+0] + bv[j+0], 0.f);
            v.y = fmaxf(acc[i][j+1] + bv[j+1], 0.f);
            v.z = fmaxf(acc[i][j+2] + bv[j+2], 0.f);
            v.w = fmaxf(acc[i][j+3] + bv[j+3], 0.f);
            *(float4*)(C + (size_t)(row0+i)*N + col0 + j) = v;
        }
    }
}

// ===========================================================================
// Row softmax over m
// ===========================================================================
__global__ __launch_bounds__(256)
void softmax_rows(float* __restrict__ S) {
    const size_t row = blockIdx.x;
    float* p = S + row * (size_t)SEQ;
    const int tid = threadIdx.x;
    float v[8];
    float mx = -INFINITY;
    #pragma unroll
    for (int i = 0; i < 8; i++) { v[i] = p[tid + i*256]; mx = fmaxf(mx, v[i]); }
    __shared__ float red_max[8];
    __shared__ float red_sum[8];
    #pragma unroll
    for (int o = 16; o > 0; o >>= 1) mx = fmaxf(mx, __shfl_xor_sync(~0u, mx, o));
    if ((tid & 31) == 0) red_max[tid >> 5] = mx;
    __syncthreads();
    if (tid < 32) {
        float t = (tid < 8) ? red_max[tid] : -INFINITY;
        #pragma unroll
        for (int o = 4; o > 0; o >>= 1) t = fmaxf(t, __shfl_xor_sync(~0u, t, o));
        if (tid == 0) red_max[0] = t;
    }
    __syncthreads();
    mx = red_max[0];
    float s = 0.f;
    #pragma unroll
    for (int i = 0; i < 8; i++) { v[i] = __expf(v[i] - mx); s += v[i]; }
    #pragma unroll
    for (int o = 16; o > 0; o >>= 1) s += __shfl_xor_sync(~0u, s, o);
    if ((tid & 31) == 0) red_sum[tid >> 5] = s;
    __syncthreads();
    if (tid < 32) {
        float t = (tid < 8) ? red_sum[tid] : 0.f;
        #pragma unroll
        for (int o = 4; o > 0; o >>= 1) t += __shfl_xor_sync(~0u, t, o);
        if (tid == 0) red_sum[0] = t;
    }
    __syncthreads();
    const float inv = 1.f / red_sum[0];
    #pragma unroll
    for (int i = 0; i < 8; i++) p[tid + i*256] = v[i] * inv;
}

// ===========================================================================
extern "C" void kernel_launch(void* const* d_in, const int* in_sizes, int n_in,
                              void* d_out, int out_size) {
    const float* x  = (const float*)d_in[0];
    const float* Wq = (const float*)d_in[1];
    const float* bq = (const float*)d_in[2];
    const float* Wk = (const float*)d_in[3];
    const float* bk = (const float*)d_in[4];
    const float* Wm = (const float*)d_in[5];
    const float* bm = (const float*)d_in[6];
    float* out = (float*)d_out;

    float *Q, *K, *S, *ATT;
    cudaGetSymbolAddress((void**)&Q,   g_Q);
    cudaGetSymbolAddress((void**)&K,   g_K);
    cudaGetSymbolAddress((void**)&S,   g_S);
    cudaGetSymbolAddress((void**)&ATT, g_ATT);

    static int attr_done = 0;
    if (!attr_done) {
        cudaFuncSetAttribute(gemm_s_tc,   cudaFuncAttributeMaxDynamicSharedMemorySize, SMEM_TC_BYTES);
        cudaFuncSetAttribute(gemm_att_tc, cudaFuncAttributeMaxDynamicSharedMemorySize, SMEM_TC_BYTES);
        attr_done = 1;
    }

    const dim3 blk(256);

    // projections
    const dim3 g1(CH / BN, MTOT / BM);
    gemm_nn_bias_relu<<<g1, blk>>>(x, Wq, bq, Q, MTOT, CH, CH);
    gemm_nn_bias_relu<<<g1, blk>>>(x, Wk, bk, K, MTOT, CH, CH);

    // S = K @ Q^T
    const dim3 g2(SEQ / 128, SEQ / 128, Bsz);
    gemm_s_tc<<<g2, blk, SMEM_TC_BYTES>>>(K, Q, S);

    // softmax over m
    softmax_rows<<<Bsz * SEQ, blk>>>(S);

    // ATT = sum_n P[n,m] V[n,h]   (V = Q)
    const dim3 g3(SEQ / 128, CH / 128, Bsz);
    gemm_att_tc<<<g3, blk, SMEM_TC_BYTES>>>(S, Q, ATT);

    // out = relu(ATT @ Wm + bm)
    gemm_nn_bias_relu<<<g1, blk>>>(ATT, Wm, bm, out, MTOT, CH, CH);
}

// round 5
// speedup vs baseline: 2.0787x; 1.1315x over previous
#include <cuda_runtime.h>
#include <cuda_bf16.h>
#include <math.h>
#include <stdint.h>

// ---------------------------------------------------------------------------
// Attention_28372553957894 — R5: all five GEMMs on HMMA (bf16 hi/lo split)
//   q = relu(x@Wq+bq); k = relu(x@Wk+bk); v = q            (mma.sync)
//   S[b,n,m] = k_n . q_m                                    (mma.sync)
//   P = softmax_m(S)                                        (SIMT, HBM-bound)
//   att[b,m,h] = sum_n P[n,m] v[n,h]                        (mma.sync)
//   out = relu(att@Wm+bm)                                   (mma.sync)
// ---------------------------------------------------------------------------

#define Bsz   8
#define SEQ   2048
#define CH    256
#define MTOT  (Bsz*SEQ)

__device__ float g_Q[MTOT * CH];
__device__ float g_K[MTOT * CH];
__device__ float g_S[Bsz * SEQ * SEQ];
__device__ float g_ATT[MTOT * CH];

// ===========================================================================
// helpers
// ===========================================================================
__device__ __forceinline__ uint32_t s2u(const void* p) {
    uint32_t a;
    asm("{ .reg .u64 t; cvta.to.shared.u64 t, %1; cvt.u32.u64 %0, t; }"
        : "=r"(a) : "l"(p));
    return a;
}
// 128B-row tiles
__device__ __forceinline__ uint32_t swz(uint32_t o)    { return o ^ ((o >> 3) & 0x70); }
// 256B-row tiles
__device__ __forceinline__ uint32_t swz256(uint32_t o) { return o ^ ((o >> 4) & 0x70); }

__device__ __forceinline__ void ldsm_x4(uint32_t& r0, uint32_t& r1, uint32_t& r2,
                                        uint32_t& r3, uint32_t addr) {
    asm volatile("ldmatrix.sync.aligned.m8n8.x4.shared.b16 {%0,%1,%2,%3}, [%4];"
                 : "=r"(r0), "=r"(r1), "=r"(r2), "=r"(r3) : "r"(addr));
}
__device__ __forceinline__ void ldsm_x4t(uint32_t& r0, uint32_t& r1, uint32_t& r2,
                                         uint32_t& r3, uint32_t addr) {
    asm volatile("ldmatrix.sync.aligned.m8n8.x4.trans.shared.b16 {%0,%1,%2,%3}, [%4];"
                 : "=r"(r0), "=r"(r1), "=r"(r2), "=r"(r3) : "r"(addr));
}

#define MMA16816(c, a, b0v, b1v)                                               \
    asm volatile(                                                              \
        "mma.sync.aligned.m16n8k16.row.col.f32.bf16.bf16.f32 "                 \
        "{%0,%1,%2,%3}, {%4,%5,%6,%7}, {%8,%9}, {%0,%1,%2,%3};"                \
        : "+f"((c)[0]), "+f"((c)[1]), "+f"((c)[2]), "+f"((c)[3])               \
        : "r"((a)[0]), "r"((a)[1]), "r"((a)[2]), "r"((a)[3]),                  \
          "r"(b0v), "r"(b1v))

__device__ __forceinline__ uint32_t pack_bf2(__nv_bfloat16 a, __nv_bfloat16 b) {
    __nv_bfloat162 t = __halves2bfloat162(a, b);
    return *reinterpret_cast<uint32_t*>(&t);
}
__device__ __forceinline__ void split1(float x, __nv_bfloat16& h, __nv_bfloat16& l) {
    h = __float2bfloat16(x);
    l = __float2bfloat16(x - __bfloat162float(h));
}

// SMEM tile offsets (16 KB each)
#define SM_A_HI  0
#define SM_A_LO  16384
#define SM_B_HI  32768
#define SM_B_LO  49152
#define SMEM_TC_BYTES 65536

// ===========================================================================
// S = K @ Q^T per batch.  CTA tile: 128 n-rows x 128 m-cols. k over CH=256.
// ===========================================================================
__global__ __launch_bounds__(256)
void gemm_s_tc(const float* __restrict__ Kg, const float* __restrict__ Qg,
               float* __restrict__ Sg) {
    extern __shared__ char smem[];
    const uint32_t sb = s2u(smem);
    const int tid = threadIdx.x, lane = tid & 31, wid = tid >> 5;
    const int b  = blockIdx.z;
    const int m0 = blockIdx.x * 128;
    const int n0 = blockIdx.y * 128;
    const float* A = Kg + (size_t)b * SEQ * CH;
    const float* B = Qg + (size_t)b * SEQ * CH;
    float*       C = Sg + (size_t)b * SEQ * SEQ;

    const int wm = (wid & 3) * 32;
    const int wn = (wid >> 2) * 64;

    float acc[2][8][4] = {};

    for (int kc = 0; kc < 4; kc++) {
        const int k0 = kc * 64;
        #pragma unroll
        for (int i = 0; i < 8; i++) {
            int e = tid + i * 256, r = e >> 4, c4 = e & 15;
            uint32_t so = swz((uint32_t)(r * 128 + c4 * 8));
            {
                float4 v = *(const float4*)(A + (size_t)(n0 + r) * CH + k0 + c4 * 4);
                __nv_bfloat16 h0,h1,h2,h3,l0,l1,l2,l3;
                split1(v.x,h0,l0); split1(v.y,h1,l1); split1(v.z,h2,l2); split1(v.w,h3,l3);
                uint2 uh = { pack_bf2(h0,h1), pack_bf2(h2,h3) };
                uint2 ul = { pack_bf2(l0,l1), pack_bf2(l2,l3) };
                *(uint2*)(smem + SM_A_HI + so) = uh;
                *(uint2*)(smem + SM_A_LO + so) = ul;
            }
            {
                float4 v = *(const float4*)(B + (size_t)(m0 + r) * CH + k0 + c4 * 4);
                __nv_bfloat16 h0,h1,h2,h3,l0,l1,l2,l3;
                split1(v.x,h0,l0); split1(v.y,h1,l1); split1(v.z,h2,l2); split1(v.w,h3,l3);
                uint2 uh = { pack_bf2(h0,h1), pack_bf2(h2,h3) };
                uint2 ul = { pack_bf2(l0,l1), pack_bf2(l2,l3) };
                *(uint2*)(smem + SM_B_HI + so) = uh;
                *(uint2*)(smem + SM_B_LO + so) = ul;
            }
        }
        __syncthreads();

        #pragma unroll
        for (int ks = 0; ks < 4; ks++) {
            const uint32_t kb  = ks * 32;
            const uint32_t sel = (lane >> 4) << 4;
            uint32_t ao0 = swz((uint32_t)((wm +      (lane & 15)) * 128) + kb + sel);
            uint32_t ao1 = swz((uint32_t)((wm + 16 + (lane & 15)) * 128) + kb + sel);
            uint32_t ah0[4], al0[4], ah1[4], al1[4];
            ldsm_x4(ah0[0],ah0[1],ah0[2],ah0[3], sb + SM_A_HI + ao0);
            ldsm_x4(al0[0],al0[1],al0[2],al0[3], sb + SM_A_LO + ao0);
            ldsm_x4(ah1[0],ah1[1],ah1[2],ah1[3], sb + SM_A_HI + ao1);
            ldsm_x4(al1[0],al1[1],al1[2],al1[3], sb + SM_A_LO + ao1);
            #pragma unroll
            for (int nq = 0; nq < 4; nq++) {
                uint32_t bo = swz((uint32_t)((wn + nq * 16 + (lane & 15)) * 128) + kb + sel);
                uint32_t bh[4], bl[4];
                ldsm_x4(bh[0],bh[1],bh[2],bh[3], sb + SM_B_HI + bo);
                ldsm_x4(bl[0],bl[1],bl[2],bl[3], sb + SM_B_LO + bo);
                MMA16816(acc[0][nq*2  ], ah0, bh[0], bh[2]);
                MMA16816(acc[0][nq*2  ], ah0, bl[0], bl[2]);
                MMA16816(acc[0][nq*2  ], al0, bh[0], bh[2]);
                MMA16816(acc[0][nq*2+1], ah0, bh[1], bh[3]);
                MMA16816(acc[0][nq*2+1], ah0, bl[1], bl[3]);
                MMA16816(acc[0][nq*2+1], al0, bh[1], bh[3]);
                MMA16816(acc[1][nq*2  ], ah1, bh[0], bh[2]);
                MMA16816(acc[1][nq*2  ], ah1, bl[0], bl[2]);
                MMA16816(acc[1][nq*2  ], al1, bh[0], bh[2]);
                MMA16816(acc[1][nq*2+1], ah1, bh[1], bh[3]);
                MMA16816(acc[1][nq*2+1], ah1, bl[1], bl[3]);
                MMA16816(acc[1][nq*2+1], al1, bh[1], bh[3]);
            }
        }
        __syncthreads();
    }

    #pragma unroll
    for (int mi = 0; mi < 2; mi++) {
        #pragma unroll
        for (int g = 0; g < 8; g++) {
            const int row = n0 + wm + mi * 16 + (lane >> 2);
            const int col = m0 + wn + g * 8 + (lane & 3) * 2;
            float2 v0 = { acc[mi][g][0], acc[mi][g][1] };
            float2 v1 = { acc[mi][g][2], acc[mi][g][3] };
            *(float2*)(C + (size_t)row * SEQ + col)        = v0;
            *(float2*)(C + (size_t)(row + 8) * SEQ + col)  = v1;
        }
    }
}

// ===========================================================================
// ATT[m,h] = sum_n P[n,m] V[n,h] per batch. CTA: 128 m x 128 h. n-chunks of 64.
// ===========================================================================
__global__ __launch_bounds__(256)
void gemm_att_tc(const float* __restrict__ Pg, const float* __restrict__ Vg,
                 float* __restrict__ ATTg) {
    extern __shared__ char smem[];
    const uint32_t sb = s2u(smem);
    const int tid = threadIdx.x, lane = tid & 31, wid = tid >> 5;
    const int b  = blockIdx.z;
    const int m0 = blockIdx.x * 128;
    const int h0 = blockIdx.y * 128;
    const float* P = Pg + (size_t)b * SEQ * SEQ;
    const float* V = Vg + (size_t)b * SEQ * CH;
    float*       C = ATTg + (size_t)b * SEQ * CH;

    const int wm = (wid & 3) * 32;
    const int wn = (wid >> 2) * 64;

    float acc[2][8][4] = {};

    for (int kc = 0; kc < 32; kc++) {
        const int nb = kc * 64;
        #pragma unroll
        for (int i = 0; i < 8; i++) {
            int e = tid + i * 256, r = e >> 5, c4 = e & 31;
            uint32_t so = swz256((uint32_t)(r * 256 + c4 * 8));
            {
                float4 v = *(const float4*)(P + (size_t)(nb + r) * SEQ + m0 + c4 * 4);
                __nv_bfloat16 h0_,h1_,h2_,h3_,l0_,l1_,l2_,l3_;
                split1(v.x,h0_,l0_); split1(v.y,h1_,l1_); split1(v.z,h2_,l2_); split1(v.w,h3_,l3_);
                uint2 uh = { pack_bf2(h0_,h1_), pack_bf2(h2_,h3_) };
                uint2 ul = { pack_bf2(l0_,l1_), pack_bf2(l2_,l3_) };
                *(uint2*)(smem + SM_A_HI + so) = uh;
                *(uint2*)(smem + SM_A_LO + so) = ul;
            }
            {
                float4 v = *(const float4*)(V + (size_t)(nb + r) * CH + h0 + c4 * 4);
                __nv_bfloat16 h0_,h1_,h2_,h3_,l0_,l1_,l2_,l3_;
                split1(v.x,h0_,l0_); split1(v.y,h1_,l1_); split1(v.z,h2_,l2_); split1(v.w,h3_,l3_);
                uint2 uh = { pack_bf2(h0_,h1_), pack_bf2(h2_,h3_) };
                uint2 ul = { pack_bf2(l0_,l1_), pack_bf2(l2_,l3_) };
                *(uint2*)(smem + SM_B_HI + so) = uh;
                *(uint2*)(smem + SM_B_LO + so) = ul;
            }
        }
        __syncthreads();

        #pragma unroll
        for (int ks = 0; ks < 4; ks++) {
            const int kk = ks * 16;
            uint32_t ah0[4], al0[4], ah1[4], al1[4];
            {
                const int arow = kk + ((lane >> 4) << 3) + (lane & 7);
                #pragma unroll
                for (int mi = 0; mi < 2; mi++) {
                    const int acol = wm + mi * 16 + (((lane >> 3) & 1) << 3);
                    uint32_t ao = swz256((uint32_t)(arow * 256 + acol * 2));
                    if (mi == 0) {
                        ldsm_x4t(ah0[0],ah0[1],ah0[2],ah0[3], sb + SM_A_HI + ao);
                        ldsm_x4t(al0[0],al0[1],al0[2],al0[3], sb + SM_A_LO + ao);
                    } else {
                        ldsm_x4t(ah1[0],ah1[1],ah1[2],ah1[3], sb + SM_A_HI + ao);
                        ldsm_x4t(al1[0],al1[1],al1[2],al1[3], sb + SM_A_LO + ao);
                    }
                }
            }
            #pragma unroll
            for (int nq = 0; nq < 4; nq++) {
                const int brow = kk + (lane & 15);
                const int bcol = wn + nq * 16 + ((lane >> 4) << 3);
                uint32_t bo = swz256((uint32_t)(brow * 256 + bcol * 2));
                uint32_t bh[4], bl[4];
                ldsm_x4t(bh[0],bh[1],bh[2],bh[3], sb + SM_B_HI + bo);
                ldsm_x4t(bl[0],bl[1],bl[2],bl[3], sb + SM_B_LO + bo);
                MMA16816(acc[0][nq*2  ], ah0, bh[0], bh[1]);
                MMA16816(acc[0][nq*2  ], ah0, bl[0], bl[1]);
                MMA16816(acc[0][nq*2  ], al0, bh[0], bh[1]);
                MMA16816(acc[0][nq*2+1], ah0, bh[2], bh[3]);
                MMA16816(acc[0][nq*2+1], ah0, bl[2], bl[3]);
                MMA16816(acc[0][nq*2+1], al0, bh[2], bh[3]);
                MMA16816(acc[1][nq*2  ], ah1, bh[0], bh[1]);
                MMA16816(acc[1][nq*2  ], ah1, bl[0], bl[1]);
                MMA16816(acc[1][nq*2  ], al1, bh[0], bh[1]);
                MMA16816(acc[1][nq*2+1], ah1, bh[2], bh[3]);
                MMA16816(acc[1][nq*2+1], ah1, bl[2], bl[3]);
                MMA16816(acc[1][nq*2+1], al1, bh[2], bh[3]);
            }
        }
        __syncthreads();
    }

    #pragma unroll
    for (int mi = 0; mi < 2; mi++) {
        #pragma unroll
        for (int g = 0; g < 8; g++) {
            const int row = m0 + wm + mi * 16 + (lane >> 2);
            const int col = h0 + wn + g * 8 + (lane & 3) * 2;
            float2 v0 = { acc[mi][g][0], acc[mi][g][1] };
            float2 v1 = { acc[mi][g][2], acc[mi][g][3] };
            *(float2*)(C + (size_t)row * CH + col)       = v0;
            *(float2*)(C + (size_t)(row + 8) * CH + col) = v1;
        }
    }
}

// ===========================================================================
// NN GEMM on HMMA: C[M,N] = relu(A[M,K] @ W[K,N] + bias[N])
// A: k-major (non-trans ldmatrix, 128B-row tiles).
// W: contraction-major [k][n] (trans ldmatrix, 256B-row tiles).
// CTA tile 128x128; K = 256 in 4 chunks of 64.
// ===========================================================================
__global__ __launch_bounds__(256)
void gemm_nn_tc(const float* __restrict__ A, const float* __restrict__ W,
                const float* __restrict__ bias, float* __restrict__ C,
                int M, int N, int K) {
    extern __shared__ char smem[];
    const uint32_t sb = s2u(smem);
    const int tid = threadIdx.x, lane = tid & 31, wid = tid >> 5;
    const int m0 = blockIdx.y * 128;
    const int n0 = blockIdx.x * 128;

    const int wm = (wid & 3) * 32;
    const int wn = (wid >> 2) * 64;

    float acc[2][8][4] = {};

    for (int kc = 0; kc < 4; kc++) {
        const int k0 = kc * 64;
        // stage A: 128 m-rows x 64 k-cols (k-major, 128B rows, swz)
        #pragma unroll
        for (int i = 0; i < 8; i++) {
            int e = tid + i * 256, r = e >> 4, c4 = e & 15;
            uint32_t so = swz((uint32_t)(r * 128 + c4 * 8));
            float4 v = *(const float4*)(A + (size_t)(m0 + r) * K + k0 + c4 * 4);
            __nv_bfloat16 h0,h1,h2,h3,l0,l1,l2,l3;
            split1(v.x,h0,l0); split1(v.y,h1,l1); split1(v.z,h2,l2); split1(v.w,h3,l3);
            uint2 uh = { pack_bf2(h0,h1), pack_bf2(h2,h3) };
            uint2 ul = { pack_bf2(l0,l1), pack_bf2(l2,l3) };
            *(uint2*)(smem + SM_A_HI + so) = uh;
            *(uint2*)(smem + SM_A_LO + so) = ul;
        }
        // stage W: 64 k-rows x 128 n-cols (contraction-major, 256B rows, swz256)
        #pragma unroll
        for (int i = 0; i < 8; i++) {
            int e = tid + i * 256, r = e >> 5, c4 = e & 31;
            uint32_t so = swz256((uint32_t)(r * 256 + c4 * 8));
            float4 v = *(const float4*)(W + (size_t)(k0 + r) * N + n0 + c4 * 4);
            __nv_bfloat16 h0,h1,h2,h3,l0,l1,l2,l3;
            split1(v.x,h0,l0); split1(v.y,h1,l1); split1(v.z,h2,l2); split1(v.w,h3,l3);
            uint2 uh = { pack_bf2(h0,h1), pack_bf2(h2,h3) };
            uint2 ul = { pack_bf2(l0,l1), pack_bf2(l2,l3) };
            *(uint2*)(smem + SM_B_HI + so) = uh;
            *(uint2*)(smem + SM_B_LO + so) = ul;
        }
        __syncthreads();

        #pragma unroll
        for (int ks = 0; ks < 4; ks++) {
            const uint32_t kb  = ks * 32;
            const uint32_t sel = (lane >> 4) << 4;
            const int kk = ks * 16;
            // A fragments (non-trans)
            uint32_t ao0 = swz((uint32_t)((wm +      (lane & 15)) * 128) + kb + sel);
            uint32_t ao1 = swz((uint32_t)((wm + 16 + (lane & 15)) * 128) + kb + sel);
            uint32_t ah0[4], al0[4], ah1[4], al1[4];
            ldsm_x4(ah0[0],ah0[1],ah0[2],ah0[3], sb + SM_A_HI + ao0);
            ldsm_x4(al0[0],al0[1],al0[2],al0[3], sb + SM_A_LO + ao0);
            ldsm_x4(ah1[0],ah1[1],ah1[2],ah1[3], sb + SM_A_HI + ao1);
            ldsm_x4(al1[0],al1[1],al1[2],al1[3], sb + SM_A_LO + ao1);
            // B fragments (trans) over 4 n16 quads
            #pragma unroll
            for (int nq = 0; nq < 4; nq++) {
                const int brow = kk + (lane & 15);
                const int bcol = wn + nq * 16 + ((lane >> 4) << 3);
                uint32_t bo = swz256((uint32_t)(brow * 256 + bcol * 2));
                uint32_t bh[4], bl[4];
                ldsm_x4t(bh[0],bh[1],bh[2],bh[3], sb + SM_B_HI + bo);
                ldsm_x4t(bl[0],bl[1],bl[2],bl[3], sb + SM_B_LO + bo);
                MMA16816(acc[0][nq*2  ], ah0, bh[0], bh[1]);
                MMA16816(acc[0][nq*2  ], ah0, bl[0], bl[1]);
                MMA16816(acc[0][nq*2  ], al0, bh[0], bh[1]);
                MMA16816(acc[0][nq*2+1], ah0, bh[2], bh[3]);
                MMA16816(acc[0][nq*2+1], ah0, bl[2], bl[3]);
                MMA16816(acc[0][nq*2+1], al0, bh[2], bh[3]);
                MMA16816(acc[1][nq*2  ], ah1, bh[0], bh[1]);
                MMA16816(acc[1][nq*2  ], ah1, bl[0], bl[1]);
                MMA16816(acc[1][nq*2  ], al1, bh[0], bh[1]);
                MMA16816(acc[1][nq*2+1], ah1, bh[2], bh[3]);
                MMA16816(acc[1][nq*2+1], ah1, bl[2], bl[3]);
                MMA16816(acc[1][nq*2+1], al1, bh[2], bh[3]);
            }
        }
        __syncthreads();
    }

    // epilogue: bias + relu
    #pragma unroll
    for (int mi = 0; mi < 2; mi++) {
        #pragma unroll
        for (int g = 0; g < 8; g++) {
            const int row = m0 + wm + mi * 16 + (lane >> 2);
            const int col = n0 + wn + g * 8 + (lane & 3) * 2;
            const float b0 = bias[col], b1 = bias[col + 1];
            float2 v0 = { fmaxf(acc[mi][g][0] + b0, 0.f),
                          fmaxf(acc[mi][g][1] + b1, 0.f) };
            float2 v1 = { fmaxf(acc[mi][g][2] + b0, 0.f),
                          fmaxf(acc[mi][g][3] + b1, 0.f) };
            *(float2*)(C + (size_t)row * N + col)       = v0;
            *(float2*)(C + (size_t)(row + 8) * N + col) = v1;
        }
    }
}

// ===========================================================================
// Row softmax over m (HBM-roofline bound already)
// ===========================================================================
__global__ __launch_bounds__(256)
void softmax_rows(float* __restrict__ S) {
    const size_t row = blockIdx.x;
    float* p = S + row * (size_t)SEQ;
    const int tid = threadIdx.x;
    float v[8];
    float mx = -INFINITY;
    #pragma unroll
    for (int i = 0; i < 8; i++) { v[i] = p[tid + i*256]; mx = fmaxf(mx, v[i]); }
    __shared__ float red_max[8];
    __shared__ float red_sum[8];
    #pragma unroll
    for (int o = 16; o > 0; o >>= 1) mx = fmaxf(mx, __shfl_xor_sync(~0u, mx, o));
    if ((tid & 31) == 0) red_max[tid >> 5] = mx;
    __syncthreads();
    if (tid < 32) {
        float t = (tid < 8) ? red_max[tid] : -INFINITY;
        #pragma unroll
        for (int o = 4; o > 0; o >>= 1) t = fmaxf(t, __shfl_xor_sync(~0u, t, o));
        if (tid == 0) red_max[0] = t;
    }
    __syncthreads();
    mx = red_max[0];
    float s = 0.f;
    #pragma unroll
    for (int i = 0; i < 8; i++) { v[i] = __expf(v[i] - mx); s += v[i]; }
    #pragma unroll
    for (int o = 16; o > 0; o >>= 1) s += __shfl_xor_sync(~0u, s, o);
    if ((tid & 31) == 0) red_sum[tid >> 5] = s;
    __syncthreads();
    if (tid < 32) {
        float t = (tid < 8) ? red_sum[tid] : 0.f;
        #pragma unroll
        for (int o = 4; o > 0; o >>= 1) t += __shfl_xor_sync(~0u, t, o);
        if (tid == 0) red_sum[0] = t;
    }
    __syncthreads();
    const float inv = 1.f / red_sum[0];
    #pragma unroll
    for (int i = 0; i < 8; i++) p[tid + i*256] = v[i] * inv;
}

// ===========================================================================
extern "C" void kernel_launch(void* const* d_in, const int* in_sizes, int n_in,
                              void* d_out, int out_size) {
    const float* x  = (const float*)d_in[0];
    const float* Wq = (const float*)d_in[1];
    const float* bq = (const float*)d_in[2];
    const float* Wk = (const float*)d_in[3];
    const float* bk = (const float*)d_in[4];
    const float* Wm = (const float*)d_in[5];
    const float* bm = (const float*)d_in[6];
    float* out = (float*)d_out;

    float *Q, *K, *S, *ATT;
    cudaGetSymbolAddress((void**)&Q,   g_Q);
    cudaGetSymbolAddress((void**)&K,   g_K);
    cudaGetSymbolAddress((void**)&S,   g_S);
    cudaGetSymbolAddress((void**)&ATT, g_ATT);

    static int attr_done = 0;
    if (!attr_done) {
        cudaFuncSetAttribute(gemm_s_tc,   cudaFuncAttributeMaxDynamicSharedMemorySize, SMEM_TC_BYTES);
        cudaFuncSetAttribute(gemm_att_tc, cudaFuncAttributeMaxDynamicSharedMemorySize, SMEM_TC_BYTES);
        cudaFuncSetAttribute(gemm_nn_tc,  cudaFuncAttributeMaxDynamicSharedMemorySize, SMEM_TC_BYTES);
        attr_done = 1;
    }

    const dim3 blk(256);

    // projections (HMMA)
    const dim3 g1(CH / 128, MTOT / 128);               // (2, 128)
    gemm_nn_tc<<<g1, blk, SMEM_TC_BYTES>>>(x, Wq, bq, Q, MTOT, CH, CH);
    gemm_nn_tc<<<g1, blk, SMEM_TC_BYTES>>>(x, Wk, bk, K, MTOT, CH, CH);

    // S = K @ Q^T
    const dim3 g2(SEQ / 128, SEQ / 128, Bsz);
    gemm_s_tc<<<g2, blk, SMEM_TC_BYTES>>>(K, Q, S);

    // softmax over m
    softmax_rows<<<Bsz * SEQ, blk>>>(S);

    // ATT = sum_n P[n,m] V[n,h]   (V = Q)
    const dim3 g3(SEQ / 128, CH / 128, Bsz);
    gemm_att_tc<<<g3, blk, SMEM_TC_BYTES>>>(S, Q, ATT);

    // out = relu(ATT @ Wm + bm)  (HMMA)
    gemm_nn_tc<<<g1, blk, SMEM_TC_BYTES>>>(ATT, Wm, bm, out, MTOT, CH, CH);
}

// round 6
// speedup vs baseline: 2.1161x; 1.0180x over previous
#include <cuda_runtime.h>
#include <cuda_bf16.h>
#include <math.h>
#include <stdint.h>

// ---------------------------------------------------------------------------
// Attention_28372553957894 — R6: hi/lo bf16 operands precomputed everywhere;
// GEMM mainloops stage by pure 16B copies.
//   x,W -> split once.  proj writes Q/K as hi/lo.  softmax writes P as hi/lo.
//   att writes ATT as hi/lo.  final gemm reads ATT split, writes fp32 out.
// ---------------------------------------------------------------------------

#define Bsz   8
#define SEQ   2048
#define CH    256
#define MTOT  (Bsz*SEQ)

// fp32 scratch
__device__ float g_S[Bsz * SEQ * SEQ];                 // 134 MB
// bf16 hi/lo scratch
__device__ __nv_bfloat16 g_xh[MTOT * CH], g_xl[MTOT * CH];
__device__ __nv_bfloat16 g_Wqh[CH * CH], g_Wql[CH * CH];
__device__ __nv_bfloat16 g_Wkh[CH * CH], g_Wkl[CH * CH];
__device__ __nv_bfloat16 g_Wmh[CH * CH], g_Wml[CH * CH];
__device__ __nv_bfloat16 g_Qh[MTOT * CH], g_Ql[MTOT * CH];
__device__ __nv_bfloat16 g_Kh[MTOT * CH], g_Kl[MTOT * CH];
__device__ __nv_bfloat16 g_Ph[(size_t)Bsz * SEQ * SEQ], g_Pl[(size_t)Bsz * SEQ * SEQ];
__device__ __nv_bfloat16 g_ATTh[MTOT * CH], g_ATTl[MTOT * CH];

// ===========================================================================
// helpers
// ===========================================================================
__device__ __forceinline__ uint32_t s2u(const void* p) {
    uint32_t a;
    asm("{ .reg .u64 t; cvta.to.shared.u64 t, %1; cvt.u32.u64 %0, t; }"
        : "=r"(a) : "l"(p));
    return a;
}
__device__ __forceinline__ uint32_t swz(uint32_t o)    { return o ^ ((o >> 3) & 0x70); }
__device__ __forceinline__ uint32_t swz256(uint32_t o) { return o ^ ((o >> 4) & 0x70); }

__device__ __forceinline__ void ldsm_x4(uint32_t& r0, uint32_t& r1, uint32_t& r2,
                                        uint32_t& r3, uint32_t addr) {
    asm volatile("ldmatrix.sync.aligned.m8n8.x4.shared.b16 {%0,%1,%2,%3}, [%4];"
                 : "=r"(r0), "=r"(r1), "=r"(r2), "=r"(r3) : "r"(addr));
}
__device__ __forceinline__ void ldsm_x4t(uint32_t& r0, uint32_t& r1, uint32_t& r2,
                                         uint32_t& r3, uint32_t addr) {
    asm volatile("ldmatrix.sync.aligned.m8n8.x4.trans.shared.b16 {%0,%1,%2,%3}, [%4];"
                 : "=r"(r0), "=r"(r1), "=r"(r2), "=r"(r3) : "r"(addr));
}

#define MMA16816(c, a, b0v, b1v)                                               \
    asm volatile(                                                              \
        "mma.sync.aligned.m16n8k16.row.col.f32.bf16.bf16.f32 "                 \
        "{%0,%1,%2,%3}, {%4,%5,%6,%7}, {%8,%9}, {%0,%1,%2,%3};"                \
        : "+f"((c)[0]), "+f"((c)[1]), "+f"((c)[2]), "+f"((c)[3])               \
        : "r"((a)[0]), "r"((a)[1]), "r"((a)[2]), "r"((a)[3]),                  \
          "r"(b0v), "r"(b1v))

__device__ __forceinline__ void split1(float x, __nv_bfloat16& h, __nv_bfloat16& l) {
    h = __float2bfloat16(x);
    l = __float2bfloat16(x - __bfloat162float(h));
}
__device__ __forceinline__ __nv_bfloat162 mkbf2(__nv_bfloat16 a, __nv_bfloat16 b) {
    return __halves2bfloat162(a, b);
}

// SMEM tile offsets (16 KB each)
#define SM_A_HI  0
#define SM_A_LO  16384
#define SM_B_HI  32768
#define SM_B_LO  49152
#define SMEM_TC_BYTES 65536

// ===========================================================================
// fp32 -> (hi, lo) bf16 split, vectorized by 4
// ===========================================================================
__global__ __launch_bounds__(256)
void split_f32(const float* __restrict__ in, __nv_bfloat16* __restrict__ hi,
               __nv_bfloat16* __restrict__ lo, int n4) {
    int i = blockIdx.x * 256 + threadIdx.x;
    if (i >= n4) return;
    float4 v = ((const float4*)in)[i];
    __nv_bfloat16 h0,h1,h2,h3,l0,l1,l2,l3;
    split1(v.x,h0,l0); split1(v.y,h1,l1); split1(v.z,h2,l2); split1(v.w,h3,l3);
    __nv_bfloat162 hv[2] = { mkbf2(h0,h1), mkbf2(h2,h3) };
    __nv_bfloat162 lv[2] = { mkbf2(l0,l1), mkbf2(l2,l3) };
    ((uint2*)hi)[i] = *(uint2*)hv;
    ((uint2*)lo)[i] = *(uint2*)lv;
}

// ===========================================================================
// NN GEMM (bf16-split operands): C = relu(A @ W + bias)
//   A: [M,K] k-major hi/lo.  W: [K,N] contraction-major hi/lo.
//   Output: either fp32 C, or hi/lo bf16 pair (whichever ptrs are non-null).
// ===========================================================================
__global__ __launch_bounds__(256)
void gemm_nn_tc(const __nv_bfloat16* __restrict__ Ah, const __nv_bfloat16* __restrict__ Al,
                const __nv_bfloat16* __restrict__ Wh, const __nv_bfloat16* __restrict__ Wl,
                const float* __restrict__ bias,
                float* __restrict__ Cf,
                __nv_bfloat16* __restrict__ Chi, __nv_bfloat16* __restrict__ Clo,
                int M, int N, int K) {
    extern __shared__ char smem[];
    const uint32_t sb = s2u(smem);
    const int tid = threadIdx.x, lane = tid & 31, wid = tid >> 5;
    const int m0 = blockIdx.y * 128;
    const int n0 = blockIdx.x * 128;
    const int wm = (wid & 3) * 32;
    const int wn = (wid >> 2) * 64;

    float acc[2][8][4] = {};

    for (int kc = 0; kc < 4; kc++) {
        const int k0 = kc * 64;
        // stage A: 128 rows x 64 k bf16 (128B rows), pure copy
        #pragma unroll
        for (int i = 0; i < 4; i++) {
            int e = tid + i * 256, r = e >> 3, c = e & 7;
            size_t go = (size_t)(m0 + r) * K + k0 + c * 8;
            uint32_t so = swz((uint32_t)(r * 128 + c * 16));
            *(uint4*)(smem + SM_A_HI + so) = *(const uint4*)(Ah + go);
            *(uint4*)(smem + SM_A_LO + so) = *(const uint4*)(Al + go);
        }
        // stage W: 64 k-rows x 128 n bf16 (256B rows), pure copy
        #pragma unroll
        for (int i = 0; i < 4; i++) {
            int e = tid + i * 256, r = e >> 4, c = e & 15;
            size_t go = (size_t)(k0 + r) * N + n0 + c * 8;
            uint32_t so = swz256((uint32_t)(r * 256 + c * 16));
            *(uint4*)(smem + SM_B_HI + so) = *(const uint4*)(Wh + go);
            *(uint4*)(smem + SM_B_LO + so) = *(const uint4*)(Wl + go);
        }
        __syncthreads();

        #pragma unroll
        for (int ks = 0; ks < 4; ks++) {
            const uint32_t kb  = ks * 32;
            const uint32_t sel = (lane >> 4) << 4;
            const int kk = ks * 16;
            uint32_t ao0 = swz((uint32_t)((wm +      (lane & 15)) * 128) + kb + sel);
            uint32_t ao1 = swz((uint32_t)((wm + 16 + (lane & 15)) * 128) + kb + sel);
            uint32_t ah0[4], al0[4], ah1[4], al1[4];
            ldsm_x4(ah0[0],ah0[1],ah0[2],ah0[3], sb + SM_A_HI + ao0);
            ldsm_x4(al0[0],al0[1],al0[2],al0[3], sb + SM_A_LO + ao0);
            ldsm_x4(ah1[0],ah1[1],ah1[2],ah1[3], sb + SM_A_HI + ao1);
            ldsm_x4(al1[0],al1[1],al1[2],al1[3], sb + SM_A_LO + ao1);
            #pragma unroll
            for (int nq = 0; nq < 4; nq++) {
                const int brow = kk + (lane & 15);
                const int bcol = wn + nq * 16 + ((lane >> 4) << 3);
                uint32_t bo = swz256((uint32_t)(brow * 256 + bcol * 2));
                uint32_t bh[4], bl[4];
                ldsm_x4t(bh[0],bh[1],bh[2],bh[3], sb + SM_B_HI + bo);
                ldsm_x4t(bl[0],bl[1],bl[2],bl[3], sb + SM_B_LO + bo);
                MMA16816(acc[0][nq*2  ], ah0, bh[0], bh[1]);
                MMA16816(acc[0][nq*2  ], ah0, bl[0], bl[1]);
                MMA16816(acc[0][nq*2  ], al0, bh[0], bh[1]);
                MMA16816(acc[0][nq*2+1], ah0, bh[2], bh[3]);
                MMA16816(acc[0][nq*2+1], ah0, bl[2], bl[3]);
                MMA16816(acc[0][nq*2+1], al0, bh[2], bh[3]);
                MMA16816(acc[1][nq*2  ], ah1, bh[0], bh[1]);
                MMA16816(acc[1][nq*2  ], ah1, bl[0], bl[1]);
                MMA16816(acc[1][nq*2  ], al1, bh[0], bh[1]);
                MMA16816(acc[1][nq*2+1], ah1, bh[2], bh[3]);
                MMA16816(acc[1][nq*2+1], ah1, bl[2], bl[3]);
                MMA16816(acc[1][nq*2+1], al1, bh[2], bh[3]);
            }
        }
        __syncthreads();
    }

    #pragma unroll
    for (int mi = 0; mi < 2; mi++) {
        #pragma unroll
        for (int g = 0; g < 8; g++) {
            const int row = m0 + wm + mi * 16 + (lane >> 2);
            const int col = n0 + wn + g * 8 + (lane & 3) * 2;
            const float b0 = bias[col], b1 = bias[col + 1];
            float v00 = fmaxf(acc[mi][g][0] + b0, 0.f);
            float v01 = fmaxf(acc[mi][g][1] + b1, 0.f);
            float v10 = fmaxf(acc[mi][g][2] + b0, 0.f);
            float v11 = fmaxf(acc[mi][g][3] + b1, 0.f);
            if (Cf) {
                *(float2*)(Cf + (size_t)row * N + col)       = make_float2(v00, v01);
                *(float2*)(Cf + (size_t)(row + 8) * N + col) = make_float2(v10, v11);
            } else {
                __nv_bfloat16 h0,h1,l0,l1;
                split1(v00,h0,l0); split1(v01,h1,l1);
                *(__nv_bfloat162*)(Chi + (size_t)row * N + col) = mkbf2(h0,h1);
                *(__nv_bfloat162*)(Clo + (size_t)row * N + col) = mkbf2(l0,l1);
                split1(v10,h0,l0); split1(v11,h1,l1);
                *(__nv_bfloat162*)(Chi + (size_t)(row + 8) * N + col) = mkbf2(h0,h1);
                *(__nv_bfloat162*)(Clo + (size_t)(row + 8) * N + col) = mkbf2(l0,l1);
            }
        }
    }
}

// ===========================================================================
// S = K @ Q^T per batch (bf16-split operands, fp32 out).
// ===========================================================================
__global__ __launch_bounds__(256)
void gemm_s_tc(const __nv_bfloat16* __restrict__ Kh, const __nv_bfloat16* __restrict__ Kl,
               const __nv_bfloat16* __restrict__ Qh, const __nv_bfloat16* __restrict__ Ql,
               float* __restrict__ Sg) {
    extern __shared__ char smem[];
    const uint32_t sb = s2u(smem);
    const int tid = threadIdx.x, lane = tid & 31, wid = tid >> 5;
    const int b  = blockIdx.z;
    const int m0 = blockIdx.x * 128;
    const int n0 = blockIdx.y * 128;
    const __nv_bfloat16* Ah = Kh + (size_t)b * SEQ * CH;
    const __nv_bfloat16* Al = Kl + (size_t)b * SEQ * CH;
    const __nv_bfloat16* Bh = Qh + (size_t)b * SEQ * CH;
    const __nv_bfloat16* Bl = Ql + (size_t)b * SEQ * CH;
    float* C = Sg + (size_t)b * SEQ * SEQ;

    const int wm = (wid & 3) * 32;
    const int wn = (wid >> 2) * 64;

    float acc[2][8][4] = {};

    for (int kc = 0; kc < 4; kc++) {
        const int k0 = kc * 64;
        #pragma unroll
        for (int i = 0; i < 4; i++) {
            int e = tid + i * 256, r = e >> 3, c = e & 7;
            uint32_t so = swz((uint32_t)(r * 128 + c * 16));
            size_t goA = (size_t)(n0 + r) * CH + k0 + c * 8;
            size_t goB = (size_t)(m0 + r) * CH + k0 + c * 8;
            *(uint4*)(smem + SM_A_HI + so) = *(const uint4*)(Ah + goA);
            *(uint4*)(smem + SM_A_LO + so) = *(const uint4*)(Al + goA);
            *(uint4*)(smem + SM_B_HI + so) = *(const uint4*)(Bh + goB);
            *(uint4*)(smem + SM_B_LO + so) = *(const uint4*)(Bl + goB);
        }
        __syncthreads();

        #pragma unroll
        for (int ks = 0; ks < 4; ks++) {
            const uint32_t kb  = ks * 32;
            const uint32_t sel = (lane >> 4) << 4;
            uint32_t ao0 = swz((uint32_t)((wm +      (lane & 15)) * 128) + kb + sel);
            uint32_t ao1 = swz((uint32_t)((wm + 16 + (lane & 15)) * 128) + kb + sel);
            uint32_t ah0[4], al0[4], ah1[4], al1[4];
            ldsm_x4(ah0[0],ah0[1],ah0[2],ah0[3], sb + SM_A_HI + ao0);
            ldsm_x4(al0[0],al0[1],al0[2],al0[3], sb + SM_A_LO + ao0);
            ldsm_x4(ah1[0],ah1[1],ah1[2],ah1[3], sb + SM_A_HI + ao1);
            ldsm_x4(al1[0],al1[1],al1[2],al1[3], sb + SM_A_LO + ao1);
            #pragma unroll
            for (int nq = 0; nq < 4; nq++) {
                uint32_t bo = swz((uint32_t)((wn + nq * 16 + (lane & 15)) * 128) + kb + sel);
                uint32_t bh[4], bl[4];
                ldsm_x4(bh[0],bh[1],bh[2],bh[3], sb + SM_B_HI + bo);
                ldsm_x4(bl[0],bl[1],bl[2],bl[3], sb + SM_B_LO + bo);
                MMA16816(acc[0][nq*2  ], ah0, bh[0], bh[2]);
                MMA16816(acc[0][nq*2  ], ah0, bl[0], bl[2]);
                MMA16816(acc[0][nq*2  ], al0, bh[0], bh[2]);
                MMA16816(acc[0][nq*2+1], ah0, bh[1], bh[3]);
                MMA16816(acc[0][nq*2+1], ah0, bl[1], bl[3]);
                MMA16816(acc[0][nq*2+1], al0, bh[1], bh[3]);
                MMA16816(acc[1][nq*2  ], ah1, bh[0], bh[2]);
                MMA16816(acc[1][nq*2  ], ah1, bl[0], bl[2]);
                MMA16816(acc[1][nq*2  ], al1, bh[0], bh[2]);
                MMA16816(acc[1][nq*2+1], ah1, bh[1], bh[3]);
                MMA16816(acc[1][nq*2+1], ah1, bl[1], bl[3]);
                MMA16816(acc[1][nq*2+1], al1, bh[1], bh[3]);
            }
        }
        __syncthreads();
    }

    #pragma unroll
    for (int mi = 0; mi < 2; mi++) {
        #pragma unroll
        for (int g = 0; g < 8; g++) {
            const int row = n0 + wm + mi * 16 + (lane >> 2);
            const int col = m0 + wn + g * 8 + (lane & 3) * 2;
            *(float2*)(C + (size_t)row * SEQ + col)       = make_float2(acc[mi][g][0], acc[mi][g][1]);
            *(float2*)(C + (size_t)(row + 8) * SEQ + col) = make_float2(acc[mi][g][2], acc[mi][g][3]);
        }
    }
}

// ===========================================================================
// ATT[m,h] = sum_n P[n,m] V[n,h] per batch (split operands, split output).
// ===========================================================================
__global__ __launch_bounds__(256)
void gemm_att_tc(const __nv_bfloat16* __restrict__ Pph, const __nv_bfloat16* __restrict__ Ppl,
                 const __nv_bfloat16* __restrict__ Vh,  const __nv_bfloat16* __restrict__ Vl,
                 __nv_bfloat16* __restrict__ Oh, __nv_bfloat16* __restrict__ Ol) {
    extern __shared__ char smem[];
    const uint32_t sb = s2u(smem);
    const int tid = threadIdx.x, lane = tid & 31, wid = tid >> 5;
    const int b  = blockIdx.z;
    const int m0 = blockIdx.x * 128;
    const int h0 = blockIdx.y * 128;
    const __nv_bfloat16* Ah = Pph + (size_t)b * SEQ * SEQ;
    const __nv_bfloat16* Al = Ppl + (size_t)b * SEQ * SEQ;
    const __nv_bfloat16* Bh = Vh + (size_t)b * SEQ * CH;
    const __nv_bfloat16* Bl = Vl + (size_t)b * SEQ * CH;
    __nv_bfloat16* Ch = Oh + (size_t)b * SEQ * CH;
    __nv_bfloat16* Cl = Ol + (size_t)b * SEQ * CH;

    const int wm = (wid & 3) * 32;
    const int wn = (wid >> 2) * 64;

    float acc[2][8][4] = {};

    for (int kc = 0; kc < 32; kc++) {
        const int nb = kc * 64;
        // stage P chunk [64 n x 128 m] and V chunk [64 n x 128 h] (256B rows)
        #pragma unroll
        for (int i = 0; i < 4; i++) {
            int e = tid + i * 256, r = e >> 4, c = e & 15;
            uint32_t so = swz256((uint32_t)(r * 256 + c * 16));
            size_t goA = (size_t)(nb + r) * SEQ + m0 + c * 8;
            size_t goB = (size_t)(nb + r) * CH + h0 + c * 8;
            *(uint4*)(smem + SM_A_HI + so) = *(const uint4*)(Ah + goA);
            *(uint4*)(smem + SM_A_LO + so) = *(const uint4*)(Al + goA);
            *(uint4*)(smem + SM_B_HI + so) = *(const uint4*)(Bh + goB);
            *(uint4*)(smem + SM_B_LO + so) = *(const uint4*)(Bl + goB);
        }
        __syncthreads();

        #pragma unroll
        for (int ks = 0; ks < 4; ks++) {
            const int kk = ks * 16;
            uint32_t ah0[4], al0[4], ah1[4], al1[4];
            {
                const int arow = kk + ((lane >> 4) << 3) + (lane & 7);
                #pragma unroll
                for (int mi = 0; mi < 2; mi++) {
                    const int acol = wm + mi * 16 + (((lane >> 3) & 1) << 3);
                    uint32_t ao = swz256((uint32_t)(arow * 256 + acol * 2));
                    if (mi == 0) {
                        ldsm_x4t(ah0[0],ah0[1],ah0[2],ah0[3], sb + SM_A_HI + ao);
                        ldsm_x4t(al0[0],al0[1],al0[2],al0[3], sb + SM_A_LO + ao);
                    } else {
                        ldsm_x4t(ah1[0],ah1[1],ah1[2],ah1[3], sb + SM_A_HI + ao);
                        ldsm_x4t(al1[0],al1[1],al1[2],al1[3], sb + SM_A_LO + ao);
                    }
                }
            }
            #pragma unroll
            for (int nq = 0; nq < 4; nq++) {
                const int brow = kk + (lane & 15);
                const int bcol = wn + nq * 16 + ((lane >> 4) << 3);
                uint32_t bo = swz256((uint32_t)(brow * 256 + bcol * 2));
                uint32_t bh[4], bl[4];
                ldsm_x4t(bh[0],bh[1],bh[2],bh[3], sb + SM_B_HI + bo);
                ldsm_x4t(bl[0],bl[1],bl[2],bl[3], sb + SM_B_LO + bo);
                MMA16816(acc[0][nq*2  ], ah0, bh[0], bh[1]);
                MMA16816(acc[0][nq*2  ], ah0, bl[0], bl[1]);
                MMA16816(acc[0][nq*2  ], al0, bh[0], bh[1]);
                MMA16816(acc[0][nq*2+1], ah0, bh[2], bh[3]);
                MMA16816(acc[0][nq*2+1], ah0, bl[2], bl[3]);
                MMA16816(acc[0][nq*2+1], al0, bh[2], bh[3]);
                MMA16816(acc[1][nq*2  ], ah1, bh[0], bh[1]);
                MMA16816(acc[1][nq*2  ], ah1, bl[0], bl[1]);
                MMA16816(acc[1][nq*2  ], al1, bh[0], bh[1]);
                MMA16816(acc[1][nq*2+1], ah1, bh[2], bh[3]);
                MMA16816(acc[1][nq*2+1], ah1, bl[2], bl[3]);
                MMA16816(acc[1][nq*2+1], al1, bh[2], bh[3]);
            }
        }
        __syncthreads();
    }

    #pragma unroll
    for (int mi = 0; mi < 2; mi++) {
        #pragma unroll
        for (int g = 0; g < 8; g++) {
            const int row = m0 + wm + mi * 16 + (lane >> 2);
            const int col = h0 + wn + g * 8 + (lane & 3) * 2;
            __nv_bfloat16 h0_,h1_,l0_,l1_;
            split1(acc[mi][g][0],h0_,l0_); split1(acc[mi][g][1],h1_,l1_);
            *(__nv_bfloat162*)(Ch + (size_t)row * CH + col) = mkbf2(h0_,h1_);
            *(__nv_bfloat162*)(Cl + (size_t)row * CH + col) = mkbf2(l0_,l1_);
            split1(acc[mi][g][2],h0_,l0_); split1(acc[mi][g][3],h1_,l1_);
            *(__nv_bfloat162*)(Ch + (size_t)(row + 8) * CH + col) = mkbf2(h0_,h1_);
            *(__nv_bfloat162*)(Cl + (size_t)(row + 8) * CH + col) = mkbf2(l0_,l1_);
        }
    }
}

// ===========================================================================
// Row softmax over m; writes P as hi/lo bf16 split.
// ===========================================================================
__global__ __launch_bounds__(256)
void softmax_split(const float* __restrict__ S, __nv_bfloat16* __restrict__ Ph,
                   __nv_bfloat16* __restrict__ Pl) {
    const size_t row = blockIdx.x;
    const float* p = S + row * (size_t)SEQ;
    const int tid = threadIdx.x;
    float v[8];
    float mx = -INFINITY;
    #pragma unroll
    for (int i = 0; i < 8; i++) { v[i] = p[tid + i*256]; mx = fmaxf(mx, v[i]); }
    __shared__ float red_max[8];
    __shared__ float red_sum[8];
    #pragma unroll
    for (int o = 16; o > 0; o >>= 1) mx = fmaxf(mx, __shfl_xor_sync(~0u, mx, o));
    if ((tid & 31) == 0) red_max[tid >> 5] = mx;
    __syncthreads();
    if (tid < 32) {
        float t = (tid < 8) ? red_max[tid] : -INFINITY;
        #pragma unroll
        for (int o = 4; o > 0; o >>= 1) t = fmaxf(t, __shfl_xor_sync(~0u, t, o));
        if (tid == 0) red_max[0] = t;
    }
    __syncthreads();
    mx = red_max[0];
    float s = 0.f;
    #pragma unroll
    for (int i = 0; i < 8; i++) { v[i] = __expf(v[i] - mx); s += v[i]; }
    #pragma unroll
    for (int o = 16; o > 0; o >>= 1) s += __shfl_xor_sync(~0u, s, o);
    if ((tid & 31) == 0) red_sum[tid >> 5] = s;
    __syncthreads();
    if (tid < 32) {
        float t = (tid < 8) ? red_sum[tid] : 0.f;
        #pragma unroll
        for (int o = 4; o > 0; o >>= 1) t += __shfl_xor_sync(~0u, t, o);
        if (tid == 0) red_sum[0] = t;
    }
    __syncthreads();
    const float inv = 1.f / red_sum[0];
    __nv_bfloat16* ph = Ph + row * (size_t)SEQ;
    __nv_bfloat16* pl = Pl + row * (size_t)SEQ;
    #pragma unroll
    for (int i = 0; i < 8; i++) {
        float x = v[i] * inv;
        __nv_bfloat16 h, l;
        split1(x, h, l);
        ph[tid + i*256] = h;
        pl[tid + i*256] = l;
    }
}

// ===========================================================================
extern "C" void kernel_launch(void* const* d_in, const int* in_sizes, int n_in,
                              void* d_out, int out_size) {
    const float* x  = (const float*)d_in[0];
    const float* Wq = (const float*)d_in[1];
    const float* bq = (const float*)d_in[2];
    const float* Wk = (const float*)d_in[3];
    const float* bk = (const float*)d_in[4];
    const float* Wm = (const float*)d_in[5];
    const float* bm = (const float*)d_in[6];
    float* out = (float*)d_out;

    float* S;
    __nv_bfloat16 *xh, *xl, *Wqh, *Wql, *Wkh, *Wkl, *Wmh, *Wml;
    __nv_bfloat16 *Qh, *Ql, *Kh, *Kl, *Ph, *Pl, *ATTh, *ATTl;
    cudaGetSymbolAddress((void**)&S,    g_S);
    cudaGetSymbolAddress((void**)&xh,   g_xh);   cudaGetSymbolAddress((void**)&xl,   g_xl);
    cudaGetSymbolAddress((void**)&Wqh,  g_Wqh);  cudaGetSymbolAddress((void**)&Wql,  g_Wql);
    cudaGetSymbolAddress((void**)&Wkh,  g_Wkh);  cudaGetSymbolAddress((void**)&Wkl,  g_Wkl);
    cudaGetSymbolAddress((void**)&Wmh,  g_Wmh);  cudaGetSymbolAddress((void**)&Wml,  g_Wml);
    cudaGetSymbolAddress((void**)&Qh,   g_Qh);   cudaGetSymbolAddress((void**)&Ql,   g_Ql);
    cudaGetSymbolAddress((void**)&Kh,   g_Kh);   cudaGetSymbolAddress((void**)&Kl,   g_Kl);
    cudaGetSymbolAddress((void**)&Ph,   g_Ph);   cudaGetSymbolAddress((void**)&Pl,   g_Pl);
    cudaGetSymbolAddress((void**)&ATTh, g_ATTh); cudaGetSymbolAddress((void**)&ATTl, g_ATTl);

    static int attr_done = 0;
    if (!attr_done) {
        cudaFuncSetAttribute(gemm_s_tc,   cudaFuncAttributeMaxDynamicSharedMemorySize, SMEM_TC_BYTES);
        cudaFuncSetAttribute(gemm_att_tc, cudaFuncAttributeMaxDynamicSharedMemorySize, SMEM_TC_BYTES);
        cudaFuncSetAttribute(gemm_nn_tc,  cudaFuncAttributeMaxDynamicSharedMemorySize, SMEM_TC_BYTES);
        attr_done = 1;
    }

    const dim3 blk(256);

    // preconvert x and weights to hi/lo bf16
    split_f32<<<(MTOT * CH / 4 + 255) / 256, blk>>>(x,  xh,  xl,  MTOT * CH / 4);
    split_f32<<<(CH * CH / 4 + 255) / 256,   blk>>>(Wq, Wqh, Wql, CH * CH / 4);
    split_f32<<<(CH * CH / 4 + 255) / 256,   blk>>>(Wk, Wkh, Wkl, CH * CH / 4);
    split_f32<<<(CH * CH / 4 + 255) / 256,   blk>>>(Wm, Wmh, Wml, CH * CH / 4);

    // projections -> Q, K splits
    const dim3 g1(CH / 128, MTOT / 128);
    gemm_nn_tc<<<g1, blk, SMEM_TC_BYTES>>>(xh, xl, Wqh, Wql, bq, nullptr, Qh, Ql, MTOT, CH, CH);
    gemm_nn_tc<<<g1, blk, SMEM_TC_BYTES>>>(xh, xl, Wkh, Wkl, bk, nullptr, Kh, Kl, MTOT, CH, CH);

    // S = K @ Q^T
    const dim3 g2(SEQ / 128, SEQ / 128, Bsz);
    gemm_s_tc<<<g2, blk, SMEM_TC_BYTES>>>(Kh, Kl, Qh, Ql, S);

    // softmax over m -> P splits
    softmax_split<<<Bsz * SEQ, blk>>>(S, Ph, Pl);

    // ATT = sum_n P[n,m] V[n,h]  (V = Q)
    const dim3 g3(SEQ / 128, CH / 128, Bsz);
    gemm_att_tc<<<g3, blk, SMEM_TC_BYTES>>>(Ph, Pl, Qh, Ql, ATTh, ATTl);

    // out = relu(ATT @ Wm + bm)
    gemm_nn_tc<<<g1, blk, SMEM_TC_BYTES>>>(ATTh, ATTl, Wmh, Wml, bm, out, nullptr, nullptr, MTOT, CH, CH);
}

// round 7
// speedup vs baseline: 2.5290x; 1.1951x over previous
#include <cuda_runtime.h>
#include <cuda_bf16.h>
#include <math.h>
#include <stdint.h>

// ---------------------------------------------------------------------------
// Attention_28372553957894 — R7:
//   3-term bf16 split kept on error-amplified paths (projections, S=K@Q^T).
//   Single-bf16 HMMA for ATT = P @ V (post-softmax errors average out).
// ---------------------------------------------------------------------------

#define Bsz   8
#define SEQ   2048
#define CH    256
#define MTOT  (Bsz*SEQ)

// fp32 scratch
__device__ float g_S[Bsz * SEQ * SEQ];                 // 134 MB
// bf16 scratch
__device__ __nv_bfloat16 g_xh[MTOT * CH], g_xl[MTOT * CH];
__device__ __nv_bfloat16 g_Wqh[CH * CH], g_Wql[CH * CH];
__device__ __nv_bfloat16 g_Wkh[CH * CH], g_Wkl[CH * CH];
__device__ __nv_bfloat16 g_Wmh[CH * CH], g_Wml[CH * CH];
__device__ __nv_bfloat16 g_Qh[MTOT * CH], g_Ql[MTOT * CH];
__device__ __nv_bfloat16 g_Kh[MTOT * CH], g_Kl[MTOT * CH];
__device__ __nv_bfloat16 g_Ph[(size_t)Bsz * SEQ * SEQ];
__device__ __nv_bfloat16 g_ATTh[MTOT * CH], g_ATTl[MTOT * CH];

// ===========================================================================
// helpers
// ===========================================================================
__device__ __forceinline__ uint32_t s2u(const void* p) {
    uint32_t a;
    asm("{ .reg .u64 t; cvta.to.shared.u64 t, %1; cvt.u32.u64 %0, t; }"
        : "=r"(a) : "l"(p));
    return a;
}
__device__ __forceinline__ uint32_t swz(uint32_t o)    { return o ^ ((o >> 3) & 0x70); }
__device__ __forceinline__ uint32_t swz256(uint32_t o) { return o ^ ((o >> 4) & 0x70); }

__device__ __forceinline__ void ldsm_x4(uint32_t& r0, uint32_t& r1, uint32_t& r2,
                                        uint32_t& r3, uint32_t addr) {
    asm volatile("ldmatrix.sync.aligned.m8n8.x4.shared.b16 {%0,%1,%2,%3}, [%4];"
                 : "=r"(r0), "=r"(r1), "=r"(r2), "=r"(r3) : "r"(addr));
}
__device__ __forceinline__ void ldsm_x4t(uint32_t& r0, uint32_t& r1, uint32_t& r2,
                                         uint32_t& r3, uint32_t addr) {
    asm volatile("ldmatrix.sync.aligned.m8n8.x4.trans.shared.b16 {%0,%1,%2,%3}, [%4];"
                 : "=r"(r0), "=r"(r1), "=r"(r2), "=r"(r3) : "r"(addr));
}

#define MMA16816(c, a, b0v, b1v)                                               \
    asm volatile(                                                              \
        "mma.sync.aligned.m16n8k16.row.col.f32.bf16.bf16.f32 "                 \
        "{%0,%1,%2,%3}, {%4,%5,%6,%7}, {%8,%9}, {%0,%1,%2,%3};"                \
        : "+f"((c)[0]), "+f"((c)[1]), "+f"((c)[2]), "+f"((c)[3])               \
        : "r"((a)[0]), "r"((a)[1]), "r"((a)[2]), "r"((a)[3]),                  \
          "r"(b0v), "r"(b1v))

__device__ __forceinline__ void split1(float x, __nv_bfloat16& h, __nv_bfloat16& l) {
    h = __float2bfloat16(x);
    l = __float2bfloat16(x - __bfloat162float(h));
}
__device__ __forceinline__ __nv_bfloat162 mkbf2(__nv_bfloat16 a, __nv_bfloat16 b) {
    return __halves2bfloat162(a, b);
}

// SMEM tile offsets
#define SM_A_HI  0
#define SM_A_LO  16384
#define SM_B_HI  32768
#define SM_B_LO  49152
#define SMEM_TC_BYTES 65536
// 1-term ATT kernel: A at 0, B at 16384, total 32 KB
#define SM1_A    0
#define SM1_B    16384
#define SMEM_ATT_BYTES 32768

// ===========================================================================
// fp32 -> (hi, lo) bf16 split
// ===========================================================================
__global__ __launch_bounds__(256)
void split_f32(const float* __restrict__ in, __nv_bfloat16* __restrict__ hi,
               __nv_bfloat16* __restrict__ lo, int n4) {
    int i = blockIdx.x * 256 + threadIdx.x;
    if (i >= n4) return;
    float4 v = ((const float4*)in)[i];
    __nv_bfloat16 h0,h1,h2,h3,l0,l1,l2,l3;
    split1(v.x,h0,l0); split1(v.y,h1,l1); split1(v.z,h2,l2); split1(v.w,h3,l3);
    __nv_bfloat162 hv[2] = { mkbf2(h0,h1), mkbf2(h2,h3) };
    __nv_bfloat162 lv[2] = { mkbf2(l0,l1), mkbf2(l2,l3) };
    ((uint2*)hi)[i] = *(uint2*)hv;
    ((uint2*)lo)[i] = *(uint2*)lv;
}

// ===========================================================================
// NN GEMM (3-term split): C = relu(A @ W + bias); out fp32 or hi/lo pair
// ===========================================================================
__global__ __launch_bounds__(256)
void gemm_nn_tc(const __nv_bfloat16* __restrict__ Ah, const __nv_bfloat16* __restrict__ Al,
                const __nv_bfloat16* __restrict__ Wh, const __nv_bfloat16* __restrict__ Wl,
                const float* __restrict__ bias,
                float* __restrict__ Cf,
                __nv_bfloat16* __restrict__ Chi, __nv_bfloat16* __restrict__ Clo,
                int M, int N, int K) {
    extern __shared__ char smem[];
    const uint32_t sb = s2u(smem);
    const int tid = threadIdx.x, lane = tid & 31, wid = tid >> 5;
    const int m0 = blockIdx.y * 128;
    const int n0 = blockIdx.x * 128;
    const int wm = (wid & 3) * 32;
    const int wn = (wid >> 2) * 64;

    float acc[2][8][4] = {};

    for (int kc = 0; kc < 4; kc++) {
        const int k0 = kc * 64;
        #pragma unroll
        for (int i = 0; i < 4; i++) {
            int e = tid + i * 256, r = e >> 3, c = e & 7;
            size_t go = (size_t)(m0 + r) * K + k0 + c * 8;
            uint32_t so = swz((uint32_t)(r * 128 + c * 16));
            *(uint4*)(smem + SM_A_HI + so) = *(const uint4*)(Ah + go);
            *(uint4*)(smem + SM_A_LO + so) = *(const uint4*)(Al + go);
        }
        #pragma unroll
        for (int i = 0; i < 4; i++) {
            int e = tid + i * 256, r = e >> 4, c = e & 15;
            size_t go = (size_t)(k0 + r) * N + n0 + c * 8;
            uint32_t so = swz256((uint32_t)(r * 256 + c * 16));
            *(uint4*)(smem + SM_B_HI + so) = *(const uint4*)(Wh + go);
            *(uint4*)(smem + SM_B_LO + so) = *(const uint4*)(Wl + go);
        }
        __syncthreads();

        #pragma unroll
        for (int ks = 0; ks < 4; ks++) {
            const uint32_t kb  = ks * 32;
            const uint32_t sel = (lane >> 4) << 4;
            const int kk = ks * 16;
            uint32_t ao0 = swz((uint32_t)((wm +      (lane & 15)) * 128) + kb + sel);
            uint32_t ao1 = swz((uint32_t)((wm + 16 + (lane & 15)) * 128) + kb + sel);
            uint32_t ah0[4], al0[4], ah1[4], al1[4];
            ldsm_x4(ah0[0],ah0[1],ah0[2],ah0[3], sb + SM_A_HI + ao0);
            ldsm_x4(al0[0],al0[1],al0[2],al0[3], sb + SM_A_LO + ao0);
            ldsm_x4(ah1[0],ah1[1],ah1[2],ah1[3], sb + SM_A_HI + ao1);
            ldsm_x4(al1[0],al1[1],al1[2],al1[3], sb + SM_A_LO + ao1);
            #pragma unroll
            for (int nq = 0; nq < 4; nq++) {
                const int brow = kk + (lane & 15);
                const int bcol = wn + nq * 16 + ((lane >> 4) << 3);
                uint32_t bo = swz256((uint32_t)(brow * 256 + bcol * 2));
                uint32_t bh[4], bl[4];
                ldsm_x4t(bh[0],bh[1],bh[2],bh[3], sb + SM_B_HI + bo);
                ldsm_x4t(bl[0],bl[1],bl[2],bl[3], sb + SM_B_LO + bo);
                MMA16816(acc[0][nq*2  ], ah0, bh[0], bh[1]);
                MMA16816(acc[0][nq*2  ], ah0, bl[0], bl[1]);
                MMA16816(acc[0][nq*2  ], al0, bh[0], bh[1]);
                MMA16816(acc[0][nq*2+1], ah0, bh[2], bh[3]);
                MMA16816(acc[0][nq*2+1], ah0, bl[2], bl[3]);
                MMA16816(acc[0][nq*2+1], al0, bh[2], bh[3]);
                MMA16816(acc[1][nq*2  ], ah1, bh[0], bh[1]);
                MMA16816(acc[1][nq*2  ], ah1, bl[0], bl[1]);
                MMA16816(acc[1][nq*2  ], al1, bh[0], bh[1]);
                MMA16816(acc[1][nq*2+1], ah1, bh[2], bh[3]);
                MMA16816(acc[1][nq*2+1], ah1, bl[2], bl[3]);
                MMA16816(acc[1][nq*2+1], al1, bh[2], bh[3]);
            }
        }
        __syncthreads();
    }

    #pragma unroll
    for (int mi = 0; mi < 2; mi++) {
        #pragma unroll
        for (int g = 0; g < 8; g++) {
            const int row = m0 + wm + mi * 16 + (lane >> 2);
            const int col = n0 + wn + g * 8 + (lane & 3) * 2;
            const float b0 = bias[col], b1 = bias[col + 1];
            float v00 = fmaxf(acc[mi][g][0] + b0, 0.f);
            float v01 = fmaxf(acc[mi][g][1] + b1, 0.f);
            float v10 = fmaxf(acc[mi][g][2] + b0, 0.f);
            float v11 = fmaxf(acc[mi][g][3] + b1, 0.f);
            if (Cf) {
                *(float2*)(Cf + (size_t)row * N + col)       = make_float2(v00, v01);
                *(float2*)(Cf + (size_t)(row + 8) * N + col) = make_float2(v10, v11);
            } else {
                __nv_bfloat16 h0,h1,l0,l1;
                split1(v00,h0,l0); split1(v01,h1,l1);
                *(__nv_bfloat162*)(Chi + (size_t)row * N + col) = mkbf2(h0,h1);
                *(__nv_bfloat162*)(Clo + (size_t)row * N + col) = mkbf2(l0,l1);
                split1(v10,h0,l0); split1(v11,h1,l1);
                *(__nv_bfloat162*)(Chi + (size_t)(row + 8) * N + col) = mkbf2(h0,h1);
                *(__nv_bfloat162*)(Clo + (size_t)(row + 8) * N + col) = mkbf2(l0,l1);
            }
        }
    }
}

// ===========================================================================
// S = K @ Q^T per batch (3-term split, fp32 out)
// ===========================================================================
__global__ __launch_bounds__(256)
void gemm_s_tc(const __nv_bfloat16* __restrict__ Kh, const __nv_bfloat16* __restrict__ Kl,
               const __nv_bfloat16* __restrict__ Qh, const __nv_bfloat16* __restrict__ Ql,
               float* __restrict__ Sg) {
    extern __shared__ char smem[];
    const uint32_t sb = s2u(smem);
    const int tid = threadIdx.x, lane = tid & 31, wid = tid >> 5;
    const int b  = blockIdx.z;
    const int m0 = blockIdx.x * 128;
    const int n0 = blockIdx.y * 128;
    const __nv_bfloat16* Ah = Kh + (size_t)b * SEQ * CH;
    const __nv_bfloat16* Al = Kl + (size_t)b * SEQ * CH;
    const __nv_bfloat16* Bh = Qh + (size_t)b * SEQ * CH;
    const __nv_bfloat16* Bl = Ql + (size_t)b * SEQ * CH;
    float* C = Sg + (size_t)b * SEQ * SEQ;

    const int wm = (wid & 3) * 32;
    const int wn = (wid >> 2) * 64;

    float acc[2][8][4] = {};

    for (int kc = 0; kc < 4; kc++) {
        const int k0 = kc * 64;
        #pragma unroll
        for (int i = 0; i < 4; i++) {
            int e = tid + i * 256, r = e >> 3, c = e & 7;
            uint32_t so = swz((uint32_t)(r * 128 + c * 16));
            size_t goA = (size_t)(n0 + r) * CH + k0 + c * 8;
            size_t goB = (size_t)(m0 + r) * CH + k0 + c * 8;
            *(uint4*)(smem + SM_A_HI + so) = *(const uint4*)(Ah + goA);
            *(uint4*)(smem + SM_A_LO + so) = *(const uint4*)(Al + goA);
            *(uint4*)(smem + SM_B_HI + so) = *(const uint4*)(Bh + goB);
            *(uint4*)(smem + SM_B_LO + so) = *(const uint4*)(Bl + goB);
        }
        __syncthreads();

        #pragma unroll
        for (int ks = 0; ks < 4; ks++) {
            const uint32_t kb  = ks * 32;
            const uint32_t sel = (lane >> 4) << 4;
            uint32_t ao0 = swz((uint32_t)((wm +      (lane & 15)) * 128) + kb + sel);
            uint32_t ao1 = swz((uint32_t)((wm + 16 + (lane & 15)) * 128) + kb + sel);
            uint32_t ah0[4], al0[4], ah1[4], al1[4];
            ldsm_x4(ah0[0],ah0[1],ah0[2],ah0[3], sb + SM_A_HI + ao0);
            ldsm_x4(al0[0],al0[1],al0[2],al0[3], sb + SM_A_LO + ao0);
            ldsm_x4(ah1[0],ah1[1],ah1[2],ah1[3], sb + SM_A_HI + ao1);
            ldsm_x4(al1[0],al1[1],al1[2],al1[3], sb + SM_A_LO + ao1);
            #pragma unroll
            for (int nq = 0; nq < 4; nq++) {
                uint32_t bo = swz((uint32_t)((wn + nq * 16 + (lane & 15)) * 128) + kb + sel);
                uint32_t bh[4], bl[4];
                ldsm_x4(bh[0],bh[1],bh[2],bh[3], sb + SM_B_HI + bo);
                ldsm_x4(bl[0],bl[1],bl[2],bl[3], sb + SM_B_LO + bo);
                MMA16816(acc[0][nq*2  ], ah0, bh[0], bh[2]);
                MMA16816(acc[0][nq*2  ], ah0, bl[0], bl[2]);
                MMA16816(acc[0][nq*2  ], al0, bh[0], bh[2]);
                MMA16816(acc[0][nq*2+1], ah0, bh[1], bh[3]);
                MMA16816(acc[0][nq*2+1], ah0, bl[1], bl[3]);
                MMA16816(acc[0][nq*2+1], al0, bh[1], bh[3]);
                MMA16816(acc[1][nq*2  ], ah1, bh[0], bh[2]);
                MMA16816(acc[1][nq*2  ], ah1, bl[0], bl[2]);
                MMA16816(acc[1][nq*2  ], al1, bh[0], bh[2]);
                MMA16816(acc[1][nq*2+1], ah1, bh[1], bh[3]);
                MMA16816(acc[1][nq*2+1], ah1, bl[1], bl[3]);
                MMA16816(acc[1][nq*2+1], al1, bh[1], bh[3]);
            }
        }
        __syncthreads();
    }

    #pragma unroll
    for (int mi = 0; mi < 2; mi++) {
        #pragma unroll
        for (int g = 0; g < 8; g++) {
            const int row = n0 + wm + mi * 16 + (lane >> 2);
            const int col = m0 + wn + g * 8 + (lane & 3) * 2;
            *(float2*)(C + (size_t)row * SEQ + col)       = make_float2(acc[mi][g][0], acc[mi][g][1]);
            *(float2*)(C + (size_t)(row + 8) * SEQ + col) = make_float2(acc[mi][g][2], acc[mi][g][3]);
        }
    }
}

// ===========================================================================
// ATT[m,h] = sum_n P[n,m] V[n,h] per batch — SINGLE bf16 term.
// ===========================================================================
__global__ __launch_bounds__(256)
void gemm_att_tc(const __nv_bfloat16* __restrict__ Pph,
                 const __nv_bfloat16* __restrict__ Vh,
                 __nv_bfloat16* __restrict__ Oh, __nv_bfloat16* __restrict__ Ol) {
    extern __shared__ char smem[];
    const uint32_t sb = s2u(smem);
    const int tid = threadIdx.x, lane = tid & 31, wid = tid >> 5;
    const int b  = blockIdx.z;
    const int m0 = blockIdx.x * 128;
    const int h0 = blockIdx.y * 128;
    const __nv_bfloat16* Ah = Pph + (size_t)b * SEQ * SEQ;
    const __nv_bfloat16* Bh = Vh + (size_t)b * SEQ * CH;
    __nv_bfloat16* Ch = Oh + (size_t)b * SEQ * CH;
    __nv_bfloat16* Cl = Ol + (size_t)b * SEQ * CH;

    const int wm = (wid & 3) * 32;
    const int wn = (wid >> 2) * 64;

    float acc[2][8][4] = {};

    for (int kc = 0; kc < 32; kc++) {
        const int nb = kc * 64;
        // stage P chunk [64 n x 128 m] and V chunk [64 n x 128 h] (256B rows)
        #pragma unroll
        for (int i = 0; i < 4; i++) {
            int e = tid + i * 256, r = e >> 4, c = e & 15;
            uint32_t so = swz256((uint32_t)(r * 256 + c * 16));
            size_t goA = (size_t)(nb + r) * SEQ + m0 + c * 8;
            size_t goB = (size_t)(nb + r) * CH + h0 + c * 8;
            *(uint4*)(smem + SM1_A + so) = *(const uint4*)(Ah + goA);
            *(uint4*)(smem + SM1_B + so) = *(const uint4*)(Bh + goB);
        }
        __syncthreads();

        #pragma unroll
        for (int ks = 0; ks < 4; ks++) {
            const int kk = ks * 16;
            uint32_t ah0[4], ah1[4];
            {
                const int arow = kk + ((lane >> 4) << 3) + (lane & 7);
                const int ac0 = wm + (((lane >> 3) & 1) << 3);
                const int ac1 = ac0 + 16;
                ldsm_x4t(ah0[0],ah0[1],ah0[2],ah0[3],
                         sb + SM1_A + swz256((uint32_t)(arow * 256 + ac0 * 2)));
                ldsm_x4t(ah1[0],ah1[1],ah1[2],ah1[3],
                         sb + SM1_A + swz256((uint32_t)(arow * 256 + ac1 * 2)));
            }
            #pragma unroll
            for (int nq = 0; nq < 4; nq++) {
                const int brow = kk + (lane & 15);
                const int bcol = wn + nq * 16 + ((lane >> 4) << 3);
                uint32_t bo = swz256((uint32_t)(brow * 256 + bcol * 2));
                uint32_t bh[4];
                ldsm_x4t(bh[0],bh[1],bh[2],bh[3], sb + SM1_B + bo);
                MMA16816(acc[0][nq*2  ], ah0, bh[0], bh[1]);
                MMA16816(acc[0][nq*2+1], ah0, bh[2], bh[3]);
                MMA16816(acc[1][nq*2  ], ah1, bh[0], bh[1]);
                MMA16816(acc[1][nq*2+1], ah1, bh[2], bh[3]);
            }
        }
        __syncthreads();
    }

    #pragma unroll
    for (int mi = 0; mi < 2; mi++) {
        #pragma unroll
        for (int g = 0; g < 8; g++) {
            const int row = m0 + wm + mi * 16 + (lane >> 2);
            const int col = h0 + wn + g * 8 + (lane & 3) * 2;
            __nv_bfloat16 h0_,h1_,l0_,l1_;
            split1(acc[mi][g][0],h0_,l0_); split1(acc[mi][g][1],h1_,l1_);
            *(__nv_bfloat162*)(Ch + (size_t)row * CH + col) = mkbf2(h0_,h1_);
            *(__nv_bfloat162*)(Cl + (size_t)row * CH + col) = mkbf2(l0_,l1_);
            split1(acc[mi][g][2],h0_,l0_); split1(acc[mi][g][3],h1_,l1_);
            *(__nv_bfloat162*)(Ch + (size_t)(row + 8) * CH + col) = mkbf2(h0_,h1_);
            *(__nv_bfloat162*)(Cl + (size_t)(row + 8) * CH + col) = mkbf2(l0_,l1_);
        }
    }
}

// ===========================================================================
// Row softmax over m; writes P as single bf16 (hi only).
// ===========================================================================
__global__ __launch_bounds__(256)
void softmax_bf16(const float* __restrict__ S, __nv_bfloat16* __restrict__ Ph) {
    const size_t row = blockIdx.x;
    const float* p = S + row * (size_t)SEQ;
    const int tid = threadIdx.x;
    float v[8];
    float mx = -INFINITY;
    #pragma unroll
    for (int i = 0; i < 8; i++) { v[i] = p[tid + i*256]; mx = fmaxf(mx, v[i]); }
    __shared__ float red_max[8];
    __shared__ float red_sum[8];
    #pragma unroll
    for (int o = 16; o > 0; o >>= 1) mx = fmaxf(mx, __shfl_xor_sync(~0u, mx, o));
    if ((tid & 31) == 0) red_max[tid >> 5] = mx;
    __syncthreads();
    if (tid < 32) {
        float t = (tid < 8) ? red_max[tid] : -INFINITY;
        #pragma unroll
        for (int o = 4; o > 0; o >>= 1) t = fmaxf(t, __shfl_xor_sync(~0u, t, o));
        if (tid == 0) red_max[0] = t;
    }
    __syncthreads();
    mx = red_max[0];
    float s = 0.f;
    #pragma unroll
    for (int i = 0; i < 8; i++) { v[i] = __expf(v[i] - mx); s += v[i]; }
    #pragma unroll
    for (int o = 16; o > 0; o >>= 1) s += __shfl_xor_sync(~0u, s, o);
    if ((tid & 31) == 0) red_sum[tid >> 5] = s;
    __syncthreads();
    if (tid < 32) {
        float t = (tid < 8) ? red_sum[tid] : 0.f;
        #pragma unroll
        for (int o = 4; o > 0; o >>= 1) t += __shfl_xor_sync(~0u, t, o);
        if (tid == 0) red_sum[0] = t;
    }
    __syncthreads();
    const float inv = 1.f / red_sum[0];
    __nv_bfloat16* ph = Ph + row * (size_t)SEQ;
    #pragma unroll
    for (int i = 0; i < 8; i += 2) {
        __nv_bfloat16 a = __float2bfloat16(v[i] * inv);
        __nv_bfloat16 b = __float2bfloat16(v[i+1] * inv);
        // adjacent i are 256 apart, not contiguous: store individually
        ph[tid + i*256]     = a;
        ph[tid + (i+1)*256] = b;
    }
}

// ===========================================================================
extern "C" void kernel_launch(void* const* d_in, const int* in_sizes, int n_in,
                              void* d_out, int out_size) {
    const float* x  = (const float*)d_in[0];
    const float* Wq = (const float*)d_in[1];
    const float* bq = (const float*)d_in[2];
    const float* Wk = (const float*)d_in[3];
    const float* bk = (const float*)d_in[4];
    const float* Wm = (const float*)d_in[5];
    const float* bm = (const float*)d_in[6];
    float* out = (float*)d_out;

    float* S;
    __nv_bfloat16 *xh, *xl, *Wqh, *Wql, *Wkh, *Wkl, *Wmh, *Wml;
    __nv_bfloat16 *Qh, *Ql, *Kh, *Kl, *Ph, *ATTh, *ATTl;
    cudaGetSymbolAddress((void**)&S,    g_S);
    cudaGetSymbolAddress((void**)&xh,   g_xh);   cudaGetSymbolAddress((void**)&xl,   g_xl);
    cudaGetSymbolAddress((void**)&Wqh,  g_Wqh);  cudaGetSymbolAddress((void**)&Wql,  g_Wql);
    cudaGetSymbolAddress((void**)&Wkh,  g_Wkh);  cudaGetSymbolAddress((void**)&Wkl,  g_Wkl);
    cudaGetSymbolAddress((void**)&Wmh,  g_Wmh);  cudaGetSymbolAddress((void**)&Wml,  g_Wml);
    cudaGetSymbolAddress((void**)&Qh,   g_Qh);   cudaGetSymbolAddress((void**)&Ql,   g_Ql);
    cudaGetSymbolAddress((void**)&Kh,   g_Kh);   cudaGetSymbolAddress((void**)&Kl,   g_Kl);
    cudaGetSymbolAddress((void**)&Ph,   g_Ph);
    cudaGetSymbolAddress((void**)&ATTh, g_ATTh); cudaGetSymbolAddress((void**)&ATTl, g_ATTl);

    static int attr_done = 0;
    if (!attr_done) {
        cudaFuncSetAttribute(gemm_s_tc,   cudaFuncAttributeMaxDynamicSharedMemorySize, SMEM_TC_BYTES);
        cudaFuncSetAttribute(gemm_att_tc, cudaFuncAttributeMaxDynamicSharedMemorySize, SMEM_ATT_BYTES);
        cudaFuncSetAttribute(gemm_nn_tc,  cudaFuncAttributeMaxDynamicSharedMemorySize, SMEM_TC_BYTES);
        attr_done = 1;
    }

    const dim3 blk(256);

    // preconvert
    split_f32<<<(MTOT * CH / 4 + 255) / 256, blk>>>(x,  xh,  xl,  MTOT * CH / 4);
    split_f32<<<(CH * CH / 4 + 255) / 256,   blk>>>(Wq, Wqh, Wql, CH * CH / 4);
    split_f32<<<(CH * CH / 4 + 255) / 256,   blk>>>(Wk, Wkh, Wkl, CH * CH / 4);
    split_f32<<<(CH * CH / 4 + 255) / 256,   blk>>>(Wm, Wmh, Wml, CH * CH / 4);

    // projections
    const dim3 g1(CH / 128, MTOT / 128);
    gemm_nn_tc<<<g1, blk, SMEM_TC_BYTES>>>(xh, xl, Wqh, Wql, bq, nullptr, Qh, Ql, MTOT, CH, CH);
    gemm_nn_tc<<<g1, blk, SMEM_TC_BYTES>>>(xh, xl, Wkh, Wkl, bk, nullptr, Kh, Kl, MTOT, CH, CH);

    // S = K @ Q^T
    const dim3 g2(SEQ / 128, SEQ / 128, Bsz);
    gemm_s_tc<<<g2, blk, SMEM_TC_BYTES>>>(Kh, Kl, Qh, Ql, S);

    // softmax -> P (bf16)
    softmax_bf16<<<Bsz * SEQ, blk>>>(S, Ph);

    // ATT = P @ V (single bf16; V = Q_hi)
    const dim3 g3(SEQ / 128, CH / 128, Bsz);
    gemm_att_tc<<<g3, blk, SMEM_ATT_BYTES>>>(Ph, Qh, ATTh, ATTl);

    // out = relu(ATT @ Wm + bm)
    gemm_nn_tc<<<g1, blk, SMEM_TC_BYTES>>>(ATTh, ATTl, Wmh, Wml, bm, out, nullptr, nullptr, MTOT, CH, CH);
}

// round 8
// speedup vs baseline: 3.6051x; 1.4255x over previous
#include <cuda_runtime.h>
#include <cuda_bf16.h>
#include <math.h>
#include <stdint.h>

// ---------------------------------------------------------------------------
// Attention_28372553957894 — R8: R7 precision config + cp.async double-buffered
// staging in all GEMM kernels.
// ---------------------------------------------------------------------------

#define Bsz   8
#define SEQ   2048
#define CH    256
#define MTOT  (Bsz*SEQ)

__device__ float g_S[Bsz * SEQ * SEQ];
__device__ __nv_bfloat16 g_xh[MTOT * CH], g_xl[MTOT * CH];
__device__ __nv_bfloat16 g_Wqh[CH * CH], g_Wql[CH * CH];
__device__ __nv_bfloat16 g_Wkh[CH * CH], g_Wkl[CH * CH];
__device__ __nv_bfloat16 g_Wmh[CH * CH], g_Wml[CH * CH];
__device__ __nv_bfloat16 g_Qh[MTOT * CH], g_Ql[MTOT * CH];
__device__ __nv_bfloat16 g_Kh[MTOT * CH], g_Kl[MTOT * CH];
__device__ __nv_bfloat16 g_Ph[(size_t)Bsz * SEQ * SEQ];
__device__ __nv_bfloat16 g_ATTh[MTOT * CH], g_ATTl[MTOT * CH];

// ===========================================================================
// helpers
// ===========================================================================
__device__ __forceinline__ uint32_t s2u(const void* p) {
    uint32_t a;
    asm("{ .reg .u64 t; cvta.to.shared.u64 t, %1; cvt.u32.u64 %0, t; }"
        : "=r"(a) : "l"(p));
    return a;
}
__device__ __forceinline__ uint32_t swz(uint32_t o)    { return o ^ ((o >> 3) & 0x70); }
__device__ __forceinline__ uint32_t swz256(uint32_t o) { return o ^ ((o >> 4) & 0x70); }

__device__ __forceinline__ void cp16(uint32_t dst, const void* src) {
    asm volatile("cp.async.cg.shared.global [%0], [%1], 16;" :: "r"(dst), "l"(src));
}
__device__ __forceinline__ void cp_commit() {
    asm volatile("cp.async.commit_group;");
}
template <int N> __device__ __forceinline__ void cp_wait() {
    asm volatile("cp.async.wait_group %0;" :: "n"(N));
}

__device__ __forceinline__ void ldsm_x4(uint32_t& r0, uint32_t& r1, uint32_t& r2,
                                        uint32_t& r3, uint32_t addr) {
    asm volatile("ldmatrix.sync.aligned.m8n8.x4.shared.b16 {%0,%1,%2,%3}, [%4];"
                 : "=r"(r0), "=r"(r1), "=r"(r2), "=r"(r3) : "r"(addr));
}
__device__ __forceinline__ void ldsm_x4t(uint32_t& r0, uint32_t& r1, uint32_t& r2,
                                         uint32_t& r3, uint32_t addr) {
    asm volatile("ldmatrix.sync.aligned.m8n8.x4.trans.shared.b16 {%0,%1,%2,%3}, [%4];"
                 : "=r"(r0), "=r"(r1), "=r"(r2), "=r"(r3) : "r"(addr));
}

#define MMA16816(c, a, b0v, b1v)                                               \
    asm volatile(                                                              \
        "mma.sync.aligned.m16n8k16.row.col.f32.bf16.bf16.f32 "                 \
        "{%0,%1,%2,%3}, {%4,%5,%6,%7}, {%8,%9}, {%0,%1,%2,%3};"                \
        : "+f"((c)[0]), "+f"((c)[1]), "+f"((c)[2]), "+f"((c)[3])               \
        : "r"((a)[0]), "r"((a)[1]), "r"((a)[2]), "r"((a)[3]),                  \
          "r"(b0v), "r"(b1v))

__device__ __forceinline__ void split1(float x, __nv_bfloat16& h, __nv_bfloat16& l) {
    h = __float2bfloat16(x);
    l = __float2bfloat16(x - __bfloat162float(h));
}
__device__ __forceinline__ __nv_bfloat162 mkbf2(__nv_bfloat16 a, __nv_bfloat16 b) {
    return __halves2bfloat162(a, b);
}

// SMEM tile offsets within one buffer (4 x 16 KB)
#define SM_A_HI  0
#define SM_A_LO  16384
#define SM_B_HI  32768
#define SM_B_LO  49152
#define S_BUF    65536
#define SMEM_DB_BYTES (2 * S_BUF)      // 128 KB for s/nn kernels
// ATT kernel buffer (2 x 16 KB tiles)
#define SM1_A    0
#define SM1_B    16384
#define ATT_BUF  32768
#define SMEM_ATT_BYTES (2 * ATT_BUF)   // 64 KB

// ===========================================================================
// fp32 -> (hi, lo) bf16 split
// ===========================================================================
__global__ __launch_bounds__(256)
void split_f32(const float* __restrict__ in, __nv_bfloat16* __restrict__ hi,
               __nv_bfloat16* __restrict__ lo, int n4) {
    int i = blockIdx.x * 256 + threadIdx.x;
    if (i >= n4) return;
    float4 v = ((const float4*)in)[i];
    __nv_bfloat16 h0,h1,h2,h3,l0,l1,l2,l3;
    split1(v.x,h0,l0); split1(v.y,h1,l1); split1(v.z,h2,l2); split1(v.w,h3,l3);
    __nv_bfloat162 hv[2] = { mkbf2(h0,h1), mkbf2(h2,h3) };
    __nv_bfloat162 lv[2] = { mkbf2(l0,l1), mkbf2(l2,l3) };
    ((uint2*)hi)[i] = *(uint2*)hv;
    ((uint2*)lo)[i] = *(uint2*)lv;
}

// ===========================================================================
// NN GEMM (3-term split, pipelined): C = relu(A @ W + bias)
// ===========================================================================
__global__ __launch_bounds__(256)
void gemm_nn_tc(const __nv_bfloat16* __restrict__ Ah, const __nv_bfloat16* __restrict__ Al,
                const __nv_bfloat16* __restrict__ Wh, const __nv_bfloat16* __restrict__ Wl,
                const float* __restrict__ bias,
                float* __restrict__ Cf,
                __nv_bfloat16* __restrict__ Chi, __nv_bfloat16* __restrict__ Clo,
                int M, int N, int K) {
    extern __shared__ char smem[];
    const uint32_t sb = s2u(smem);
    const int tid = threadIdx.x, lane = tid & 31, wid = tid >> 5;
    const int m0 = blockIdx.y * 128;
    const int n0 = blockIdx.x * 128;
    const int wm = (wid & 3) * 32;
    const int wn = (wid >> 2) * 64;

    float acc[2][8][4] = {};

    auto stage = [&](int kc, uint32_t bo) {
        const int k0 = kc * 64;
        #pragma unroll
        for (int i = 0; i < 4; i++) {
            int e = tid + i * 256, r = e >> 3, c = e & 7;
            size_t go = (size_t)(m0 + r) * K + k0 + c * 8;
            uint32_t so = swz((uint32_t)(r * 128 + c * 16));
            cp16(sb + bo + SM_A_HI + so, Ah + go);
            cp16(sb + bo + SM_A_LO + so, Al + go);
        }
        #pragma unroll
        for (int i = 0; i < 4; i++) {
            int e = tid + i * 256, r = e >> 4, c = e & 15;
            size_t go = (size_t)(k0 + r) * N + n0 + c * 8;
            uint32_t so = swz256((uint32_t)(r * 256 + c * 16));
            cp16(sb + bo + SM_B_HI + so, Wh + go);
            cp16(sb + bo + SM_B_LO + so, Wl + go);
        }
    };

    stage(0, 0);
    cp_commit();

    for (int kc = 0; kc < 4; kc++) {
        if (kc < 3) stage(kc + 1, (uint32_t)(((kc + 1) & 1) * S_BUF));
        cp_commit();
        cp_wait<1>();
        __syncthreads();
        const uint32_t bo = (uint32_t)((kc & 1) * S_BUF);

        #pragma unroll
        for (int ks = 0; ks < 4; ks++) {
            const uint32_t kb  = ks * 32;
            const uint32_t sel = (lane >> 4) << 4;
            const int kk = ks * 16;
            uint32_t ao0 = swz((uint32_t)((wm +      (lane & 15)) * 128) + kb + sel);
            uint32_t ao1 = swz((uint32_t)((wm + 16 + (lane & 15)) * 128) + kb + sel);
            uint32_t ah0[4], al0[4], ah1[4], al1[4];
            ldsm_x4(ah0[0],ah0[1],ah0[2],ah0[3], sb + bo + SM_A_HI + ao0);
            ldsm_x4(al0[0],al0[1],al0[2],al0[3], sb + bo + SM_A_LO + ao0);
            ldsm_x4(ah1[0],ah1[1],ah1[2],ah1[3], sb + bo + SM_A_HI + ao1);
            ldsm_x4(al1[0],al1[1],al1[2],al1[3], sb + bo + SM_A_LO + ao1);
            #pragma unroll
            for (int nq = 0; nq < 4; nq++) {
                const int brow = kk + (lane & 15);
                const int bcol = wn + nq * 16 + ((lane >> 4) << 3);
                uint32_t bof = swz256((uint32_t)(brow * 256 + bcol * 2));
                uint32_t bh[4], bl[4];
                ldsm_x4t(bh[0],bh[1],bh[2],bh[3], sb + bo + SM_B_HI + bof);
                ldsm_x4t(bl[0],bl[1],bl[2],bl[3], sb + bo + SM_B_LO + bof);
                MMA16816(acc[0][nq*2  ], ah0, bh[0], bh[1]);
                MMA16816(acc[0][nq*2  ], ah0, bl[0], bl[1]);
                MMA16816(acc[0][nq*2  ], al0, bh[0], bh[1]);
                MMA16816(acc[0][nq*2+1], ah0, bh[2], bh[3]);
                MMA16816(acc[0][nq*2+1], ah0, bl[2], bl[3]);
                MMA16816(acc[0][nq*2+1], al0, bh[2], bh[3]);
                MMA16816(acc[1][nq*2  ], ah1, bh[0], bh[1]);
                MMA16816(acc[1][nq*2  ], ah1, bl[0], bl[1]);
                MMA16816(acc[1][nq*2  ], al1, bh[0], bh[1]);
                MMA16816(acc[1][nq*2+1], ah1, bh[2], bh[3]);
                MMA16816(acc[1][nq*2+1], ah1, bl[2], bl[3]);
                MMA16816(acc[1][nq*2+1], al1, bh[2], bh[3]);
            }
        }
        __syncthreads();
    }

    #pragma unroll
    for (int mi = 0; mi < 2; mi++) {
        #pragma unroll
        for (int g = 0; g < 8; g++) {
            const int row = m0 + wm + mi * 16 + (lane >> 2);
            const int col = n0 + wn + g * 8 + (lane & 3) * 2;
            const float b0 = bias[col], b1 = bias[col + 1];
            float v00 = fmaxf(acc[mi][g][0] + b0, 0.f);
            float v01 = fmaxf(acc[mi][g][1] + b1, 0.f);
            float v10 = fmaxf(acc[mi][g][2] + b0, 0.f);
            float v11 = fmaxf(acc[mi][g][3] + b1, 0.f);
            if (Cf) {
                *(float2*)(Cf + (size_t)row * N + col)       = make_float2(v00, v01);
                *(float2*)(Cf + (size_t)(row + 8) * N + col) = make_float2(v10, v11);
            } else {
                __nv_bfloat16 h0,h1,l0,l1;
                split1(v00,h0,l0); split1(v01,h1,l1);
                *(__nv_bfloat162*)(Chi + (size_t)row * N + col) = mkbf2(h0,h1);
                *(__nv_bfloat162*)(Clo + (size_t)row * N + col) = mkbf2(l0,l1);
                split1(v10,h0,l0); split1(v11,h1,l1);
                *(__nv_bfloat162*)(Chi + (size_t)(row + 8) * N + col) = mkbf2(h0,h1);
                *(__nv_bfloat162*)(Clo + (size_t)(row + 8) * N + col) = mkbf2(l0,l1);
            }
        }
    }
}

// ===========================================================================
// S = K @ Q^T per batch (3-term split, pipelined, fp32 out)
// ===========================================================================
__global__ __launch_bounds__(256)
void gemm_s_tc(const __nv_bfloat16* __restrict__ Kh, const __nv_bfloat16* __restrict__ Kl,
               const __nv_bfloat16* __restrict__ Qh, const __nv_bfloat16* __restrict__ Ql,
               float* __restrict__ Sg) {
    extern __shared__ char smem[];
    const uint32_t sb = s2u(smem);
    const int tid = threadIdx.x, lane = tid & 31, wid = tid >> 5;
    const int b  = blockIdx.z;
    const int m0 = blockIdx.x * 128;
    const int n0 = blockIdx.y * 128;
    const __nv_bfloat16* Ah = Kh + (size_t)b * SEQ * CH;
    const __nv_bfloat16* Al = Kl + (size_t)b * SEQ * CH;
    const __nv_bfloat16* Bh = Qh + (size_t)b * SEQ * CH;
    const __nv_bfloat16* Bl = Ql + (size_t)b * SEQ * CH;
    float* C = Sg + (size_t)b * SEQ * SEQ;

    const int wm = (wid & 3) * 32;
    const int wn = (wid >> 2) * 64;

    float acc[2][8][4] = {};

    auto stage = [&](int kc, uint32_t bo) {
        const int k0 = kc * 64;
        #pragma unroll
        for (int i = 0; i < 4; i++) {
            int e = tid + i * 256, r = e >> 3, c = e & 7;
            uint32_t so = swz((uint32_t)(r * 128 + c * 16));
            size_t goA = (size_t)(n0 + r) * CH + k0 + c * 8;
            size_t goB = (size_t)(m0 + r) * CH + k0 + c * 8;
            cp16(sb + bo + SM_A_HI + so, Ah + goA);
            cp16(sb + bo + SM_A_LO + so, Al + goA);
            cp16(sb + bo + SM_B_HI + so, Bh + goB);
            cp16(sb + bo + SM_B_LO + so, Bl + goB);
        }
    };

    stage(0, 0);
    cp_commit();

    for (int kc = 0; kc < 4; kc++) {
        if (kc < 3) stage(kc + 1, (uint32_t)(((kc + 1) & 1) * S_BUF));
        cp_commit();
        cp_wait<1>();
        __syncthreads();
        const uint32_t bo = (uint32_t)((kc & 1) * S_BUF);

        #pragma unroll
        for (int ks = 0; ks < 4; ks++) {
            const uint32_t kb  = ks * 32;
            const uint32_t sel = (lane >> 4) << 4;
            uint32_t ao0 = swz((uint32_t)((wm +      (lane & 15)) * 128) + kb + sel);
            uint32_t ao1 = swz((uint32_t)((wm + 16 + (lane & 15)) * 128) + kb + sel);
            uint32_t ah0[4], al0[4], ah1[4], al1[4];
            ldsm_x4(ah0[0],ah0[1],ah0[2],ah0[3], sb + bo + SM_A_HI + ao0);
            ldsm_x4(al0[0],al0[1],al0[2],al0[3], sb + bo + SM_A_LO + ao0);
            ldsm_x4(ah1[0],ah1[1],ah1[2],ah1[3], sb + bo + SM_A_HI + ao1);
            ldsm_x4(al1[0],al1[1],al1[2],al1[3], sb + bo + SM_A_LO + ao1);
            #pragma unroll
            for (int nq = 0; nq < 4; nq++) {
                uint32_t bof = swz((uint32_t)((wn + nq * 16 + (lane & 15)) * 128) + kb + sel);
                uint32_t bh[4], bl[4];
                ldsm_x4(bh[0],bh[1],bh[2],bh[3], sb + bo + SM_B_HI + bof);
                ldsm_x4(bl[0],bl[1],bl[2],bl[3], sb + bo + SM_B_LO + bof);
                MMA16816(acc[0][nq*2  ], ah0, bh[0], bh[2]);
                MMA16816(acc[0][nq*2  ], ah0, bl[0], bl[2]);
                MMA16816(acc[0][nq*2  ], al0, bh[0], bh[2]);
                MMA16816(acc[0][nq*2+1], ah0, bh[1], bh[3]);
                MMA16816(acc[0][nq*2+1], ah0, bl[1], bl[3]);
                MMA16816(acc[0][nq*2+1], al0, bh[1], bh[3]);
                MMA16816(acc[1][nq*2  ], ah1, bh[0], bh[2]);
                MMA16816(acc[1][nq*2  ], ah1, bl[0], bl[2]);
                MMA16816(acc[1][nq*2  ], al1, bh[0], bh[2]);
                MMA16816(acc[1][nq*2+1], ah1, bh[1], bh[3]);
                MMA16816(acc[1][nq*2+1], ah1, bl[1], bl[3]);
                MMA16816(acc[1][nq*2+1], al1, bh[1], bh[3]);
            }
        }
        __syncthreads();
    }

    #pragma unroll
    for (int mi = 0; mi < 2; mi++) {
        #pragma unroll
        for (int g = 0; g < 8; g++) {
            const int row = n0 + wm + mi * 16 + (lane >> 2);
            const int col = m0 + wn + g * 8 + (lane & 3) * 2;
            *(float2*)(C + (size_t)row * SEQ + col)       = make_float2(acc[mi][g][0], acc[mi][g][1]);
            *(float2*)(C + (size_t)(row + 8) * SEQ + col) = make_float2(acc[mi][g][2], acc[mi][g][3]);
        }
    }
}

// ===========================================================================
// ATT[m,h] = sum_n P[n,m] V[n,h] per batch — single bf16, pipelined.
// ===========================================================================
__global__ __launch_bounds__(256)
void gemm_att_tc(const __nv_bfloat16* __restrict__ Pph,
                 const __nv_bfloat16* __restrict__ Vh,
                 __nv_bfloat16* __restrict__ Oh, __nv_bfloat16* __restrict__ Ol) {
    extern __shared__ char smem[];
    const uint32_t sb = s2u(smem);
    const int tid = threadIdx.x, lane = tid & 31, wid = tid >> 5;
    const int b  = blockIdx.z;
    const int m0 = blockIdx.x * 128;
    const int h0 = blockIdx.y * 128;
    const __nv_bfloat16* Ah = Pph + (size_t)b * SEQ * SEQ;
    const __nv_bfloat16* Bh = Vh + (size_t)b * SEQ * CH;
    __nv_bfloat16* Ch = Oh + (size_t)b * SEQ * CH;
    __nv_bfloat16* Cl = Ol + (size_t)b * SEQ * CH;

    const int wm = (wid & 3) * 32;
    const int wn = (wid >> 2) * 64;

    float acc[2][8][4] = {};

    auto stage = [&](int kc, uint32_t bo) {
        const int nb = kc * 64;
        #pragma unroll
        for (int i = 0; i < 4; i++) {
            int e = tid + i * 256, r = e >> 4, c = e & 15;
            uint32_t so = swz256((uint32_t)(r * 256 + c * 16));
            size_t goA = (size_t)(nb + r) * SEQ + m0 + c * 8;
            size_t goB = (size_t)(nb + r) * CH + h0 + c * 8;
            cp16(sb + bo + SM1_A + so, Ah + goA);
            cp16(sb + bo + SM1_B + so, Bh + goB);
        }
    };

    stage(0, 0);
    cp_commit();

    for (int kc = 0; kc < 32; kc++) {
        if (kc < 31) stage(kc + 1, (uint32_t)(((kc + 1) & 1) * ATT_BUF));
        cp_commit();
        cp_wait<1>();
        __syncthreads();
        const uint32_t bo = (uint32_t)((kc & 1) * ATT_BUF);

        #pragma unroll
        for (int ks = 0; ks < 4; ks++) {
            const int kk = ks * 16;
            uint32_t ah0[4], ah1[4];
            {
                const int arow = kk + ((lane >> 4) << 3) + (lane & 7);
                const int ac0 = wm + (((lane >> 3) & 1) << 3);
                const int ac1 = ac0 + 16;
                ldsm_x4t(ah0[0],ah0[1],ah0[2],ah0[3],
                         sb + bo + SM1_A + swz256((uint32_t)(arow * 256 + ac0 * 2)));
                ldsm_x4t(ah1[0],ah1[1],ah1[2],ah1[3],
                         sb + bo + SM1_A + swz256((uint32_t)(arow * 256 + ac1 * 2)));
            }
            #pragma unroll
            for (int nq = 0; nq < 4; nq++) {
                const int brow = kk + (lane & 15);
                const int bcol = wn + nq * 16 + ((lane >> 4) << 3);
                uint32_t bof = swz256((uint32_t)(brow * 256 + bcol * 2));
                uint32_t bh[4];
                ldsm_x4t(bh[0],bh[1],bh[2],bh[3], sb + bo + SM1_B + bof);
                MMA16816(acc[0][nq*2  ], ah0, bh[0], bh[1]);
                MMA16816(acc[0][nq*2+1], ah0, bh[2], bh[3]);
                MMA16816(acc[1][nq*2  ], ah1, bh[0], bh[1]);
                MMA16816(acc[1][nq*2+1], ah1, bh[2], bh[3]);
            }
        }
        __syncthreads();
    }

    #pragma unroll
    for (int mi = 0; mi < 2; mi++) {
        #pragma unroll
        for (int g = 0; g < 8; g++) {
            const int row = m0 + wm + mi * 16 + (lane >> 2);
            const int col = h0 + wn + g * 8 + (lane & 3) * 2;
            __nv_bfloat16 h0_,h1_,l0_,l1_;
            split1(acc[mi][g][0],h0_,l0_); split1(acc[mi][g][1],h1_,l1_);
            *(__nv_bfloat162*)(Ch + (size_t)row * CH + col) = mkbf2(h0_,h1_);
            *(__nv_bfloat162*)(Cl + (size_t)row * CH + col) = mkbf2(l0_,l1_);
            split1(acc[mi][g][2],h0_,l0_); split1(acc[mi][g][3],h1_,l1_);
            *(__nv_bfloat162*)(Ch + (size_t)(row + 8) * CH + col) = mkbf2(h0_,h1_);
            *(__nv_bfloat162*)(Cl + (size_t)(row + 8) * CH + col) = mkbf2(l0_,l1_);
        }
    }
}

// ===========================================================================
// Row softmax over m; contiguous per-thread layout, bf16 out (16B stores).
// ===========================================================================
__global__ __launch_bounds__(256)
void softmax_bf16(const float* __restrict__ S, __nv_bfloat16* __restrict__ Ph) {
    const size_t row = blockIdx.x;
    const float* p = S + row * (size_t)SEQ;
    const int tid = threadIdx.x;
    float v[8];
    {
        float4 a = *(const float4*)(p + tid * 8);
        float4 b = *(const float4*)(p + tid * 8 + 4);
        v[0]=a.x; v[1]=a.y; v[2]=a.z; v[3]=a.w;
        v[4]=b.x; v[5]=b.y; v[6]=b.z; v[7]=b.w;
    }
    float mx = v[0];
    #pragma unroll
    for (int i = 1; i < 8; i++) mx = fmaxf(mx, v[i]);
    __shared__ float red_max[8];
    __shared__ float red_sum[8];
    #pragma unroll
    for (int o = 16; o > 0; o >>= 1) mx = fmaxf(mx, __shfl_xor_sync(~0u, mx, o));
    if ((tid & 31) == 0) red_max[tid >> 5] = mx;
    __syncthreads();
    if (tid < 32) {
        float t = (tid < 8) ? red_max[tid] : -INFINITY;
        #pragma unroll
        for (int o = 4; o > 0; o >>= 1) t = fmaxf(t, __shfl_xor_sync(~0u, t, o));
        if (tid == 0) red_max[0] = t;
    }
    __syncthreads();
    mx = red_max[0];
    float s = 0.f;
    #pragma unroll
    for (int i = 0; i < 8; i++) { v[i] = __expf(v[i] - mx); s += v[i]; }
    #pragma unroll
    for (int o = 16; o > 0; o >>= 1) s += __shfl_xor_sync(~0u, s, o);
    if ((tid & 31) == 0) red_sum[tid >> 5] = s;
    __syncthreads();
    if (tid < 32) {
        float t = (tid < 8) ? red_sum[tid] : 0.f;
        #pragma unroll
        for (int o = 4; o > 0; o >>= 1) t += __shfl_xor_sync(~0u, t, o);
        if (tid == 0) red_sum[0] = t;
    }
    __syncthreads();
    const float inv = 1.f / red_sum[0];
    __nv_bfloat162 ov[4];
    #pragma unroll
    for (int i = 0; i < 4; i++) {
        ov[i] = mkbf2(__float2bfloat16(v[2*i] * inv), __float2bfloat16(v[2*i+1] * inv));
    }
    *(uint2*)(Ph + row * (size_t)SEQ + tid * 8)     = *(uint2*)&ov[0];
    *(uint2*)(Ph + row * (size_t)SEQ + tid * 8 + 4) = *(uint2*)&ov[2];
}

// ===========================================================================
extern "C" void kernel_launch(void* const* d_in, const int* in_sizes, int n_in,
                              void* d_out, int out_size) {
    const float* x  = (const float*)d_in[0];
    const float* Wq = (const float*)d_in[1];
    const float* bq = (const float*)d_in[2];
    const float* Wk = (const float*)d_in[3];
    const float* bk = (const float*)d_in[4];
    const float* Wm = (const float*)d_in[5];
    const float* bm = (const float*)d_in[6];
    float* out = (float*)d_out;

    float* S;
    __nv_bfloat16 *xh, *xl, *Wqh, *Wql, *Wkh, *Wkl, *Wmh, *Wml;
    __nv_bfloat16 *Qh, *Ql, *Kh, *Kl, *Ph, *ATTh, *ATTl;
    cudaGetSymbolAddress((void**)&S,    g_S);
    cudaGetSymbolAddress((void**)&xh,   g_xh);   cudaGetSymbolAddress((void**)&xl,   g_xl);
    cudaGetSymbolAddress((void**)&Wqh,  g_Wqh);  cudaGetSymbolAddress((void**)&Wql,  g_Wql);
    cudaGetSymbolAddress((void**)&Wkh,  g_Wkh);  cudaGetSymbolAddress((void**)&Wkl,  g_Wkl);
    cudaGetSymbolAddress((void**)&Wmh,  g_Wmh);  cudaGetSymbolAddress((void**)&Wml,  g_Wml);
    cudaGetSymbolAddress((void**)&Qh,   g_Qh);   cudaGetSymbolAddress((void**)&Ql,   g_Ql);
    cudaGetSymbolAddress((void**)&Kh,   g_Kh);   cudaGetSymbolAddress((void**)&Kl,   g_Kl);
    cudaGetSymbolAddress((void**)&Ph,   g_Ph);
    cudaGetSymbolAddress((void**)&ATTh, g_ATTh); cudaGetSymbolAddress((void**)&ATTl, g_ATTl);

    static int attr_done = 0;
    if (!attr_done) {
        cudaFuncSetAttribute(gemm_s_tc,   cudaFuncAttributeMaxDynamicSharedMemorySize, SMEM_DB_BYTES);
        cudaFuncSetAttribute(gemm_att_tc, cudaFuncAttributeMaxDynamicSharedMemorySize, SMEM_ATT_BYTES);
        cudaFuncSetAttribute(gemm_nn_tc,  cudaFuncAttributeMaxDynamicSharedMemorySize, SMEM_DB_BYTES);
        attr_done = 1;
    }

    const dim3 blk(256);

    // preconvert
    split_f32<<<(MTOT * CH / 4 + 255) / 256, blk>>>(x,  xh,  xl,  MTOT * CH / 4);
    split_f32<<<(CH * CH / 4 + 255) / 256,   blk>>>(Wq, Wqh, Wql, CH * CH / 4);
    split_f32<<<(CH * CH / 4 + 255) / 256,   blk>>>(Wk, Wkh, Wkl, CH * CH / 4);
    split_f32<<<(CH * CH / 4 + 255) / 256,   blk>>>(Wm, Wmh, Wml, CH * CH / 4);

    // projections
    const dim3 g1(CH / 128, MTOT / 128);
    gemm_nn_tc<<<g1, blk, SMEM_DB_BYTES>>>(xh, xl, Wqh, Wql, bq, nullptr, Qh, Ql, MTOT, CH, CH);
    gemm_nn_tc<<<g1, blk, SMEM_DB_BYTES>>>(xh, xl, Wkh, Wkl, bk, nullptr, Kh, Kl, MTOT, CH, CH);

    // S = K @ Q^T
    const dim3 g2(SEQ / 128, SEQ / 128, Bsz);
    gemm_s_tc<<<g2, blk, SMEM_DB_BYTES>>>(Kh, Kl, Qh, Ql, S);

    // softmax -> P (bf16)
    softmax_bf16<<<Bsz * SEQ, blk>>>(S, Ph);

    // ATT = P @ V (single bf16; V = Q_hi)
    const dim3 g3(SEQ / 128, CH / 128, Bsz);
    gemm_att_tc<<<g3, blk, SMEM_ATT_BYTES>>>(Ph, Qh, ATTh, ATTl);

    // out = relu(ATT @ Wm + bm)
    gemm_nn_tc<<<g1, blk, SMEM_DB_BYTES>>>(ATTh, ATTl, Wmh, Wml, bm, out, nullptr, nullptr, MTOT, CH, CH);
}

// round 9
// speedup vs baseline: 3.8167x; 1.0587x over previous
#include <cuda_runtime.h>
#include <cuda_bf16.h>
#include <math.h>
#include <stdint.h>

// ---------------------------------------------------------------------------
// Attention_28372553957894 — R9: R8 + 3-stage pipeline on 128KB kernels,
// term-major MMA ordering, merged q/k projection + merged weight splits.
// ---------------------------------------------------------------------------

#define Bsz   8
#define SEQ   2048
#define CH    256
#define MTOT  (Bsz*SEQ)

__device__ float g_S[Bsz * SEQ * SEQ];
__device__ __nv_bfloat16 g_xh[MTOT * CH], g_xl[MTOT * CH];
__device__ __nv_bfloat16 g_Wqh[CH * CH], g_Wql[CH * CH];
__device__ __nv_bfloat16 g_Wkh[CH * CH], g_Wkl[CH * CH];
__device__ __nv_bfloat16 g_Wmh[CH * CH], g_Wml[CH * CH];
__device__ __nv_bfloat16 g_Qh[MTOT * CH], g_Ql[MTOT * CH];
__device__ __nv_bfloat16 g_Kh[MTOT * CH], g_Kl[MTOT * CH];
__device__ __nv_bfloat16 g_Ph[(size_t)Bsz * SEQ * SEQ];
__device__ __nv_bfloat16 g_ATTh[MTOT * CH], g_ATTl[MTOT * CH];

// ===========================================================================
// helpers
// ===========================================================================
__device__ __forceinline__ uint32_t s2u(const void* p) {
    uint32_t a;
    asm("{ .reg .u64 t; cvta.to.shared.u64 t, %1; cvt.u32.u64 %0, t; }"
        : "=r"(a) : "l"(p));
    return a;
}
__device__ __forceinline__ uint32_t swz(uint32_t o)    { return o ^ ((o >> 3) & 0x70); }
__device__ __forceinline__ uint32_t swz256(uint32_t o) { return o ^ ((o >> 4) & 0x70); }

__device__ __forceinline__ void cp16(uint32_t dst, const void* src) {
    asm volatile("cp.async.cg.shared.global [%0], [%1], 16;" :: "r"(dst), "l"(src));
}
__device__ __forceinline__ void cp_commit() {
    asm volatile("cp.async.commit_group;");
}
template <int N> __device__ __forceinline__ void cp_wait() {
    asm volatile("cp.async.wait_group %0;" :: "n"(N));
}

__device__ __forceinline__ void ldsm_x4(uint32_t& r0, uint32_t& r1, uint32_t& r2,
                                        uint32_t& r3, uint32_t addr) {
    asm volatile("ldmatrix.sync.aligned.m8n8.x4.shared.b16 {%0,%1,%2,%3}, [%4];"
                 : "=r"(r0), "=r"(r1), "=r"(r2), "=r"(r3) : "r"(addr));
}
__device__ __forceinline__ void ldsm_x4t(uint32_t& r0, uint32_t& r1, uint32_t& r2,
                                         uint32_t& r3, uint32_t addr) {
    asm volatile("ldmatrix.sync.aligned.m8n8.x4.trans.shared.b16 {%0,%1,%2,%3}, [%4];"
                 : "=r"(r0), "=r"(r1), "=r"(r2), "=r"(r3) : "r"(addr));
}

#define MMA16816(c, a, b0v, b1v)                                               \
    asm volatile(                                                              \
        "mma.sync.aligned.m16n8k16.row.col.f32.bf16.bf16.f32 "                 \
        "{%0,%1,%2,%3}, {%4,%5,%6,%7}, {%8,%9}, {%0,%1,%2,%3};"                \
        : "+f"((c)[0]), "+f"((c)[1]), "+f"((c)[2]), "+f"((c)[3])               \
        : "r"((a)[0]), "r"((a)[1]), "r"((a)[2]), "r"((a)[3]),                  \
          "r"(b0v), "r"(b1v))

__device__ __forceinline__ void split1(float x, __nv_bfloat16& h, __nv_bfloat16& l) {
    h = __float2bfloat16(x);
    l = __float2bfloat16(x - __bfloat162float(h));
}
__device__ __forceinline__ __nv_bfloat162 mkbf2(__nv_bfloat16 a, __nv_bfloat16 b) {
    return __halves2bfloat162(a, b);
}

// SMEM tile offsets within one buffer (4 x 16 KB)
#define SM_A_HI  0
#define SM_A_LO  16384
#define SM_B_HI  32768
#define SM_B_LO  49152
#define S_BUF    65536
#define SMEM_3S_BYTES (3 * S_BUF)      // 192 KB: 3-stage pipeline, 1 CTA/SM
// ATT kernel buffer (2 x 16 KB tiles)
#define SM1_A    0
#define SM1_B    16384
#define ATT_BUF  32768
#define SMEM_ATT_BYTES (2 * ATT_BUF)   // 64 KB

// ===========================================================================
// fp32 -> (hi, lo) splits: one kernel handles x + 3 weight matrices.
// grid: [0, NX4) -> x ; then 3 weight segments of W4 each.
// ===========================================================================
#define NX4 (MTOT * CH / 4)
#define W4  (CH * CH / 4)
__global__ __launch_bounds__(256)
void split_all(const float* __restrict__ x,
               const float* __restrict__ Wq, const float* __restrict__ Wk,
               const float* __restrict__ Wm,
               __nv_bfloat16* __restrict__ xh, __nv_bfloat16* __restrict__ xl,
               __nv_bfloat16* __restrict__ Wqh, __nv_bfloat16* __restrict__ Wql,
               __nv_bfloat16* __restrict__ Wkh, __nv_bfloat16* __restrict__ Wkl,
               __nv_bfloat16* __restrict__ Wmh, __nv_bfloat16* __restrict__ Wml) {
    int i = blockIdx.x * 256 + threadIdx.x;
    const float* in; __nv_bfloat16 *hi, *lo; int idx;
    if (i < NX4)                { in = x;  hi = xh;  lo = xl;  idx = i; }
    else if (i < NX4 + W4)      { in = Wq; hi = Wqh; lo = Wql; idx = i - NX4; }
    else if (i < NX4 + 2 * W4)  { in = Wk; hi = Wkh; lo = Wkl; idx = i - NX4 - W4; }
    else if (i < NX4 + 3 * W4)  { in = Wm; hi = Wmh; lo = Wml; idx = i - NX4 - 2 * W4; }
    else return;
    float4 v = ((const float4*)in)[idx];
    __nv_bfloat16 h0,h1,h2,h3,l0,l1,l2,l3;
    split1(v.x,h0,l0); split1(v.y,h1,l1); split1(v.z,h2,l2); split1(v.w,h3,l3);
    __nv_bfloat162 hv[2] = { mkbf2(h0,h1), mkbf2(h2,h3) };
    __nv_bfloat162 lv[2] = { mkbf2(l0,l1), mkbf2(l2,l3) };
    ((uint2*)hi)[idx] = *(uint2*)hv;
    ((uint2*)lo)[idx] = *(uint2*)lv;
}

// ===========================================================================
// NN GEMM core (3-term split, 3-stage pipeline, term-major MMA order)
// ===========================================================================
__device__ __forceinline__
void gemm_nn_body(const __nv_bfloat16* __restrict__ Ah, const __nv_bfloat16* __restrict__ Al,
                  const __nv_bfloat16* __restrict__ Wh, const __nv_bfloat16* __restrict__ Wl,
                  const float* __restrict__ bias,
                  float* __restrict__ Cf,
                  __nv_bfloat16* __restrict__ Chi, __nv_bfloat16* __restrict__ Clo,
                  int m0, int n0, int N, int K, char* smem) {
    const uint32_t sb = s2u(smem);
    const int tid = threadIdx.x, lane = tid & 31, wid = tid >> 5;
    const int wm = (wid & 3) * 32;
    const int wn = (wid >> 2) * 64;

    float acc[2][8][4] = {};

    auto stage = [&](int kc, uint32_t bo) {
        const int k0 = kc * 64;
        #pragma unroll
        for (int i = 0; i < 4; i++) {
            int e = tid + i * 256, r = e >> 3, c = e & 7;
            size_t go = (size_t)(m0 + r) * K + k0 + c * 8;
            uint32_t so = swz((uint32_t)(r * 128 + c * 16));
            cp16(sb + bo + SM_A_HI + so, Ah + go);
            cp16(sb + bo + SM_A_LO + so, Al + go);
        }
        #pragma unroll
        for (int i = 0; i < 4; i++) {
            int e = tid + i * 256, r = e >> 4, c = e & 15;
            size_t go = (size_t)(k0 + r) * N + n0 + c * 8;
            uint32_t so = swz256((uint32_t)(r * 256 + c * 16));
            cp16(sb + bo + SM_B_HI + so, Wh + go);
            cp16(sb + bo + SM_B_LO + so, Wl + go);
        }
    };

    stage(0, 0);           cp_commit();
    stage(1, S_BUF);       cp_commit();

    for (int kc = 0; kc < 4; kc++) {
        if (kc < 2) stage(kc + 2, (uint32_t)(((kc + 2) % 3) * S_BUF));
        cp_commit();
        cp_wait<2>();
        __syncthreads();
        const uint32_t bo = (uint32_t)((kc % 3) * S_BUF);

        #pragma unroll
        for (int ks = 0; ks < 4; ks++) {
            const uint32_t kb  = ks * 32;
            const uint32_t sel = (lane >> 4) << 4;
            const int kk = ks * 16;
            uint32_t ao0 = swz((uint32_t)((wm +      (lane & 15)) * 128) + kb + sel);
            uint32_t ao1 = swz((uint32_t)((wm + 16 + (lane & 15)) * 128) + kb + sel);
            uint32_t ah0[4], al0[4], ah1[4], al1[4];
            ldsm_x4(ah0[0],ah0[1],ah0[2],ah0[3], sb + bo + SM_A_HI + ao0);
            ldsm_x4(al0[0],al0[1],al0[2],al0[3], sb + bo + SM_A_LO + ao0);
            ldsm_x4(ah1[0],ah1[1],ah1[2],ah1[3], sb + bo + SM_A_HI + ao1);
            ldsm_x4(al1[0],al1[1],al1[2],al1[3], sb + bo + SM_A_LO + ao1);
            #pragma unroll
            for (int nq = 0; nq < 4; nq++) {
                const int brow = kk + (lane & 15);
                const int bcol = wn + nq * 16 + ((lane >> 4) << 3);
                uint32_t bof = swz256((uint32_t)(brow * 256 + bcol * 2));
                uint32_t bh[4], bl[4];
                ldsm_x4t(bh[0],bh[1],bh[2],bh[3], sb + bo + SM_B_HI + bof);
                ldsm_x4t(bl[0],bl[1],bl[2],bl[3], sb + bo + SM_B_LO + bof);
                // term-major: 4 independent accs per term
                MMA16816(acc[0][nq*2  ], ah0, bh[0], bh[1]);
                MMA16816(acc[0][nq*2+1], ah0, bh[2], bh[3]);
                MMA16816(acc[1][nq*2  ], ah1, bh[0], bh[1]);
                MMA16816(acc[1][nq*2+1], ah1, bh[2], bh[3]);
                MMA16816(acc[0][nq*2  ], ah0, bl[0], bl[1]);
                MMA16816(acc[0][nq*2+1], ah0, bl[2], bl[3]);
                MMA16816(acc[1][nq*2  ], ah1, bl[0], bl[1]);
                MMA16816(acc[1][nq*2+1], ah1, bl[2], bl[3]);
                MMA16816(acc[0][nq*2  ], al0, bh[0], bh[1]);
                MMA16816(acc[0][nq*2+1], al0, bh[2], bh[3]);
                MMA16816(acc[1][nq*2  ], al1, bh[0], bh[1]);
                MMA16816(acc[1][nq*2+1], al1, bh[2], bh[3]);
            }
        }
        __syncthreads();
    }

    #pragma unroll
    for (int mi = 0; mi < 2; mi++) {
        #pragma unroll
        for (int g = 0; g < 8; g++) {
            const int row = m0 + wm + mi * 16 + (lane >> 2);
            const int col = n0 + wn + g * 8 + (lane & 3) * 2;
            const float b0 = bias[col], b1 = bias[col + 1];
            float v00 = fmaxf(acc[mi][g][0] + b0, 0.f);
            float v01 = fmaxf(acc[mi][g][1] + b1, 0.f);
            float v10 = fmaxf(acc[mi][g][2] + b0, 0.f);
            float v11 = fmaxf(acc[mi][g][3] + b1, 0.f);
            if (Cf) {
                *(float2*)(Cf + (size_t)row * N + col)       = make_float2(v00, v01);
                *(float2*)(Cf + (size_t)(row + 8) * N + col) = make_float2(v10, v11);
            } else {
                __nv_bfloat16 h0,h1,l0,l1;
                split1(v00,h0,l0); split1(v01,h1,l1);
                *(__nv_bfloat162*)(Chi + (size_t)row * N + col) = mkbf2(h0,h1);
                *(__nv_bfloat162*)(Clo + (size_t)row * N + col) = mkbf2(l0,l1);
                split1(v10,h0,l0); split1(v11,h1,l1);
                *(__nv_bfloat162*)(Chi + (size_t)(row + 8) * N + col) = mkbf2(h0,h1);
                *(__nv_bfloat162*)(Clo + (size_t)(row + 8) * N + col) = mkbf2(l0,l1);
            }
        }
    }
}

// merged q+k projection: blockIdx.z selects weight set
__global__ __launch_bounds__(256)
void gemm_qk_tc(const __nv_bfloat16* __restrict__ xh, const __nv_bfloat16* __restrict__ xl,
                const __nv_bfloat16* __restrict__ Wqh, const __nv_bfloat16* __restrict__ Wql,
                const __nv_bfloat16* __restrict__ Wkh, const __nv_bfloat16* __restrict__ Wkl,
                const float* __restrict__ bq, const float* __restrict__ bk,
                __nv_bfloat16* __restrict__ Qh, __nv_bfloat16* __restrict__ Ql,
                __nv_bfloat16* __restrict__ Kh, __nv_bfloat16* __restrict__ Kl) {
    extern __shared__ char smem[];
    const int m0 = blockIdx.y * 128;
    const int n0 = blockIdx.x * 128;
    if (blockIdx.z == 0)
        gemm_nn_body(xh, xl, Wqh, Wql, bq, nullptr, Qh, Ql, m0, n0, CH, CH, smem);
    else
        gemm_nn_body(xh, xl, Wkh, Wkl, bk, nullptr, Kh, Kl, m0, n0, CH, CH, smem);
}

// final projection: fp32 output
__global__ __launch_bounds__(256)
void gemm_out_tc(const __nv_bfloat16* __restrict__ Ah, const __nv_bfloat16* __restrict__ Al,
                 const __nv_bfloat16* __restrict__ Wh, const __nv_bfloat16* __restrict__ Wl,
                 const float* __restrict__ bias, float* __restrict__ Cf) {
    extern __shared__ char smem[];
    const int m0 = blockIdx.y * 128;
    const int n0 = blockIdx.x * 128;
    gemm_nn_body(Ah, Al, Wh, Wl, bias, Cf, nullptr, nullptr, m0, n0, CH, CH, smem);
}

// ===========================================================================
// S = K @ Q^T per batch (3-term split, 3-stage pipeline, fp32 out)
// ===========================================================================
__global__ __launch_bounds__(256)
void gemm_s_tc(const __nv_bfloat16* __restrict__ Kh, const __nv_bfloat16* __restrict__ Kl,
               const __nv_bfloat16* __restrict__ Qh, const __nv_bfloat16* __restrict__ Ql,
               float* __restrict__ Sg) {
    extern __shared__ char smem[];
    const uint32_t sb = s2u(smem);
    const int tid = threadIdx.x, lane = tid & 31, wid = tid >> 5;
    const int b  = blockIdx.z;
    const int m0 = blockIdx.x * 128;
    const int n0 = blockIdx.y * 128;
    const __nv_bfloat16* Ah = Kh + (size_t)b * SEQ * CH;
    const __nv_bfloat16* Al = Kl + (size_t)b * SEQ * CH;
    const __nv_bfloat16* Bh = Qh + (size_t)b * SEQ * CH;
    const __nv_bfloat16* Bl = Ql + (size_t)b * SEQ * CH;
    float* C = Sg + (size_t)b * SEQ * SEQ;

    const int wm = (wid & 3) * 32;
    const int wn = (wid >> 2) * 64;

    float acc[2][8][4] = {};

    auto stage = [&](int kc, uint32_t bo) {
        const int k0 = kc * 64;
        #pragma unroll
        for (int i = 0; i < 4; i++) {
            int e = tid + i * 256, r = e >> 3, c = e & 7;
            uint32_t so = swz((uint32_t)(r * 128 + c * 16));
            size_t goA = (size_t)(n0 + r) * CH + k0 + c * 8;
            size_t goB = (size_t)(m0 + r) * CH + k0 + c * 8;
            cp16(sb + bo + SM_A_HI + so, Ah + goA);
            cp16(sb + bo + SM_A_LO + so, Al + goA);
            cp16(sb + bo + SM_B_HI + so, Bh + goB);
            cp16(sb + bo + SM_B_LO + so, Bl + goB);
        }
    };

    stage(0, 0);       cp_commit();
    stage(1, S_BUF);   cp_commit();

    for (int kc = 0; kc < 4; kc++) {
        if (kc < 2) stage(kc + 2, (uint32_t)(((kc + 2) % 3) * S_BUF));
        cp_commit();
        cp_wait<2>();
        __syncthreads();
        const uint32_t bo = (uint32_t)((kc % 3) * S_BUF);

        #pragma unroll
        for (int ks = 0; ks < 4; ks++) {
            const uint32_t kb  = ks * 32;
            const uint32_t sel = (lane >> 4) << 4;
            uint32_t ao0 = swz((uint32_t)((wm +      (lane & 15)) * 128) + kb + sel);
            uint32_t ao1 = swz((uint32_t)((wm + 16 + (lane & 15)) * 128) + kb + sel);
            uint32_t ah0[4], al0[4], ah1[4], al1[4];
            ldsm_x4(ah0[0],ah0[1],ah0[2],ah0[3], sb + bo + SM_A_HI + ao0);
            ldsm_x4(al0[0],al0[1],al0[2],al0[3], sb + bo + SM_A_LO + ao0);
            ldsm_x4(ah1[0],ah1[1],ah1[2],ah1[3], sb + bo + SM_A_HI + ao1);
            ldsm_x4(al1[0],al1[1],al1[2],al1[3], sb + bo + SM_A_LO + ao1);
            #pragma unroll
            for (int nq = 0; nq < 4; nq++) {
                uint32_t bof = swz((uint32_t)((wn + nq * 16 + (lane & 15)) * 128) + kb + sel);
                uint32_t bh[4], bl[4];
                ldsm_x4(bh[0],bh[1],bh[2],bh[3], sb + bo + SM_B_HI + bof);
                ldsm_x4(bl[0],bl[1],bl[2],bl[3], sb + bo + SM_B_LO + bof);
                // term-major ordering (non-trans groups: g0={r0,r2}, g1={r1,r3})
                MMA16816(acc[0][nq*2  ], ah0, bh[0], bh[2]);
                MMA16816(acc[0][nq*2+1], ah0, bh[1], bh[3]);
                MMA16816(acc[1][nq*2  ], ah1, bh[0], bh[2]);
                MMA16816(acc[1][nq*2+1], ah1, bh[1], bh[3]);
                MMA16816(acc[0][nq*2  ], ah0, bl[0], bl[2]);
                MMA16816(acc[0][nq*2+1], ah0, bl[1], bl[3]);
                MMA16816(acc[1][nq*2  ], ah1, bl[0], bl[2]);
                MMA16816(acc[1][nq*2+1], ah1, bl[1], bl[3]);
                MMA16816(acc[0][nq*2  ], al0, bh[0], bh[2]);
                MMA16816(acc[0][nq*2+1], al0, bh[1], bh[3]);
                MMA16816(acc[1][nq*2  ], al1, bh[0], bh[2]);
                MMA16816(acc[1][nq*2+1], al1, bh[1], bh[3]);
            }
        }
        __syncthreads();
    }

    #pragma unroll
    for (int mi = 0; mi < 2; mi++) {
        #pragma unroll
        for (int g = 0; g < 8; g++) {
            const int row = n0 + wm + mi * 16 + (lane >> 2);
            const int col = m0 + wn + g * 8 + (lane & 3) * 2;
            *(float2*)(C + (size_t)row * SEQ + col)       = make_float2(acc[mi][g][0], acc[mi][g][1]);
            *(float2*)(C + (size_t)(row + 8) * SEQ + col) = make_float2(acc[mi][g][2], acc[mi][g][3]);
        }
    }
}

// ===========================================================================
// ATT[m,h] = sum_n P[n,m] V[n,h] per batch — single bf16, 2-stage pipelined.
// ===========================================================================
__global__ __launch_bounds__(256)
void gemm_att_tc(const __nv_bfloat16* __restrict__ Pph,
                 const __nv_bfloat16* __restrict__ Vh,
                 __nv_bfloat16* __restrict__ Oh, __nv_bfloat16* __restrict__ Ol) {
    extern __shared__ char smem[];
    const uint32_t sb = s2u(smem);
    const int tid = threadIdx.x, lane = tid & 31, wid = tid >> 5;
    const int b  = blockIdx.z;
    const int m0 = blockIdx.x * 128;
    const int h0 = blockIdx.y * 128;
    const __nv_bfloat16* Ah = Pph + (size_t)b * SEQ * SEQ;
    const __nv_bfloat16* Bh = Vh + (size_t)b * SEQ * CH;
    __nv_bfloat16* Ch = Oh + (size_t)b * SEQ * CH;
    __nv_bfloat16* Cl = Ol + (size_t)b * SEQ * CH;

    const int wm = (wid & 3) * 32;
    const int wn = (wid >> 2) * 64;

    float acc[2][8][4] = {};

    auto stage = [&](int kc, uint32_t bo) {
        const int nb = kc * 64;
        #pragma unroll
        for (int i = 0; i < 4; i++) {
            int e = tid + i * 256, r = e >> 4, c = e & 15;
            uint32_t so = swz256((uint32_t)(r * 256 + c * 16));
            size_t goA = (size_t)(nb + r) * SEQ + m0 + c * 8;
            size_t goB = (size_t)(nb + r) * CH + h0 + c * 8;
            cp16(sb + bo + SM1_A + so, Ah + goA);
            cp16(sb + bo + SM1_B + so, Bh + goB);
        }
    };

    stage(0, 0);
    cp_commit();

    for (int kc = 0; kc < 32; kc++) {
        if (kc < 31) stage(kc + 1, (uint32_t)(((kc + 1) & 1) * ATT_BUF));
        cp_commit();
        cp_wait<1>();
        __syncthreads();
        const uint32_t bo = (uint32_t)((kc & 1) * ATT_BUF);

        #pragma unroll
        for (int ks = 0; ks < 4; ks++) {
            const int kk = ks * 16;
            uint32_t ah0[4], ah1[4];
            {
                const int arow = kk + ((lane >> 4) << 3) + (lane & 7);
                const int ac0 = wm + (((lane >> 3) & 1) << 3);
                const int ac1 = ac0 + 16;
                ldsm_x4t(ah0[0],ah0[1],ah0[2],ah0[3],
                         sb + bo + SM1_A + swz256((uint32_t)(arow * 256 + ac0 * 2)));
                ldsm_x4t(ah1[0],ah1[1],ah1[2],ah1[3],
                         sb + bo + SM1_A + swz256((uint32_t)(arow * 256 + ac1 * 2)));
            }
            #pragma unroll
            for (int nq = 0; nq < 4; nq++) {
                const int brow = kk + (lane & 15);
                const int bcol = wn + nq * 16 + ((lane >> 4) << 3);
                uint32_t bof = swz256((uint32_t)(brow * 256 + bcol * 2));
                uint32_t bh[4];
                ldsm_x4t(bh[0],bh[1],bh[2],bh[3], sb + bo + SM1_B + bof);
                MMA16816(acc[0][nq*2  ], ah0, bh[0], bh[1]);
                MMA16816(acc[0][nq*2+1], ah0, bh[2], bh[3]);
                MMA16816(acc[1][nq*2  ], ah1, bh[0], bh[1]);
                MMA16816(acc[1][nq*2+1], ah1, bh[2], bh[3]);
            }
        }
        __syncthreads();
    }

    #pragma unroll
    for (int mi = 0; mi < 2; mi++) {
        #pragma unroll
        for (int g = 0; g < 8; g++) {
            const int row = m0 + wm + mi * 16 + (lane >> 2);
            const int col = h0 + wn + g * 8 + (lane & 3) * 2;
            __nv_bfloat16 h0_,h1_,l0_,l1_;
            split1(acc[mi][g][0],h0_,l0_); split1(acc[mi][g][1],h1_,l1_);
            *(__nv_bfloat162*)(Ch + (size_t)row * CH + col) = mkbf2(h0_,h1_);
            *(__nv_bfloat162*)(Cl + (size_t)row * CH + col) = mkbf2(l0_,l1_);
            split1(acc[mi][g][2],h0_,l0_); split1(acc[mi][g][3],h1_,l1_);
            *(__nv_bfloat162*)(Ch + (size_t)(row + 8) * CH + col) = mkbf2(h0_,h1_);
            *(__nv_bfloat162*)(Cl + (size_t)(row + 8) * CH + col) = mkbf2(l0_,l1_);
        }
    }
}

// ===========================================================================
// Row softmax over m; contiguous per-thread layout, bf16 out (16B stores).
// ===========================================================================
__global__ __launch_bounds__(256)
void softmax_bf16(const float* __restrict__ S, __nv_bfloat16* __restrict__ Ph) {
    const size_t row = blockIdx.x;
    const float* p = S + row * (size_t)SEQ;
    const int tid = threadIdx.x;
    float v[8];
    {
        float4 a = *(const float4*)(p + tid * 8);
        float4 b = *(const float4*)(p + tid * 8 + 4);
        v[0]=a.x; v[1]=a.y; v[2]=a.z; v[3]=a.w;
        v[4]=b.x; v[5]=b.y; v[6]=b.z; v[7]=b.w;
    }
    float mx = v[0];
    #pragma unroll
    for (int i = 1; i < 8; i++) mx = fmaxf(mx, v[i]);
    __shared__ float red_max[8];
    __shared__ float red_sum[8];
    #pragma unroll
    for (int o = 16; o > 0; o >>= 1) mx = fmaxf(mx, __shfl_xor_sync(~0u, mx, o));
    if ((tid & 31) == 0) red_max[tid >> 5] = mx;
    __syncthreads();
    if (tid < 32) {
        float t = (tid < 8) ? red_max[tid] : -INFINITY;
        #pragma unroll
        for (int o = 4; o > 0; o >>= 1) t = fmaxf(t, __shfl_xor_sync(~0u, t, o));
        if (tid == 0) red_max[0] = t;
    }
    __syncthreads();
    mx = red_max[0];
    float s = 0.f;
    #pragma unroll
    for (int i = 0; i < 8; i++) { v[i] = __expf(v[i] - mx); s += v[i]; }
    #pragma unroll
    for (int o = 16; o > 0; o >>= 1) s += __shfl_xor_sync(~0u, s, o);
    if ((tid & 31) == 0) red_sum[tid >> 5] = s;
    __syncthreads();
    if (tid < 32) {
        float t = (tid < 8) ? red_sum[tid] : 0.f;
        #pragma unroll
        for (int o = 4; o > 0; o >>= 1) t += __shfl_xor_sync(~0u, t, o);
        if (tid == 0) red_sum[0] = t;
    }
    __syncthreads();
    const float inv = 1.f / red_sum[0];
    __nv_bfloat162 ov[4];
    #pragma unroll
    for (int i = 0; i < 4; i++) {
        ov[i] = mkbf2(__float2bfloat16(v[2*i] * inv), __float2bfloat16(v[2*i+1] * inv));
    }
    *(uint2*)(Ph + row * (size_t)SEQ + tid * 8)     = *(uint2*)&ov[0];
    *(uint2*)(Ph + row * (size_t)SEQ + tid * 8 + 4) = *(uint2*)&ov[2];
}

// ===========================================================================
extern "C" void kernel_launch(void* const* d_in, const int* in_sizes, int n_in,
                              void* d_out, int out_size) {
    const float* x  = (const float*)d_in[0];
    const float* Wq = (const float*)d_in[1];
    const float* bq = (const float*)d_in[2];
    const float* Wk = (const float*)d_in[3];
    const float* bk = (const float*)d_in[4];
    const float* Wm = (const float*)d_in[5];
    const float* bm = (const float*)d_in[6];
    float* out = (float*)d_out;

    float* S;
    __nv_bfloat16 *xh, *xl, *Wqh, *Wql, *Wkh, *Wkl, *Wmh, *Wml;
    __nv_bfloat16 *Qh, *Ql, *Kh, *Kl, *Ph, *ATTh, *ATTl;
    cudaGetSymbolAddress((void**)&S,    g_S);
    cudaGetSymbolAddress((void**)&xh,   g_xh);   cudaGetSymbolAddress((void**)&xl,   g_xl);
    cudaGetSymbolAddress((void**)&Wqh,  g_Wqh);  cudaGetSymbolAddress((void**)&Wql,  g_Wql);
    cudaGetSymbolAddress((void**)&Wkh,  g_Wkh);  cudaGetSymbolAddress((void**)&Wkl,  g_Wkl);
    cudaGetSymbolAddress((void**)&Wmh,  g_Wmh);  cudaGetSymbolAddress((void**)&Wml,  g_Wml);
    cudaGetSymbolAddress((void**)&Qh,   g_Qh);   cudaGetSymbolAddress((void**)&Ql,   g_Ql);
    cudaGetSymbolAddress((void**)&Kh,   g_Kh);   cudaGetSymbolAddress((void**)&Kl,   g_Kl);
    cudaGetSymbolAddress((void**)&Ph,   g_Ph);
    cudaGetSymbolAddress((void**)&ATTh, g_ATTh); cudaGetSymbolAddress((void**)&ATTl, g_ATTl);

    static int attr_done = 0;
    if (!attr_done) {
        cudaFuncSetAttribute(gemm_s_tc,   cudaFuncAttributeMaxDynamicSharedMemorySize, SMEM_3S_BYTES);
        cudaFuncSetAttribute(gemm_att_tc, cudaFuncAttributeMaxDynamicSharedMemorySize, SMEM_ATT_BYTES);
        cudaFuncSetAttribute(gemm_qk_tc,  cudaFuncAttributeMaxDynamicSharedMemorySize, SMEM_3S_BYTES);
        cudaFuncSetAttribute(gemm_out_tc, cudaFuncAttributeMaxDynamicSharedMemorySize, SMEM_3S_BYTES);
        attr_done = 1;
    }

    const dim3 blk(256);

    // preconvert x + all weights in one launch
    const int total4 = NX4 + 3 * W4;
    split_all<<<(total4 + 255) / 256, blk>>>(x, Wq, Wk, Wm, xh, xl,
                                             Wqh, Wql, Wkh, Wkl, Wmh, Wml);

    // q+k projections, one launch
    const dim3 gqk(CH / 128, MTOT / 128, 2);
    gemm_qk_tc<<<gqk, blk, SMEM_3S_BYTES>>>(xh, xl, Wqh, Wql, Wkh, Wkl,
                                            bq, bk, Qh, Ql, Kh, Kl);

    // S = K @ Q^T
    const dim3 g2(SEQ / 128, SEQ / 128, Bsz);
    gemm_s_tc<<<g2, blk, SMEM_3S_BYTES>>>(Kh, Kl, Qh, Ql, S);

    // softmax -> P (bf16)
    softmax_bf16<<<Bsz * SEQ, blk>>>(S, Ph);

    // ATT = P @ V (single bf16; V = Q_hi)
    const dim3 g3(SEQ / 128, CH / 128, Bsz);
    gemm_att_tc<<<g3, blk, SMEM_ATT_BYTES>>>(Ph, Qh, ATTh, ATTl);

    // out = relu(ATT @ Wm + bm)
    const dim3 g1(CH / 128, MTOT / 128);
    gemm_out_tc<<<g1, blk, SMEM_3S_BYTES>>>(ATTh, ATTl, Wmh, Wml, bm, out);
}